// round 13
// baseline (speedup 1.0000x reference)
#include <cuda_runtime.h>
#include <cuda_fp16.h>
#include <cstdint>

#define H 128
#define W 128
#define HW 16384
#define OH 512
#define OWID 512
#define NQ (OH*OWID)

// ------------------------------ scratch (device globals, no allocation) ----
__device__ __align__(16) float g_h0[64*HW];      // fp32 NHWC (head conv out)
__device__ __align__(16) __half g_h0h[64*HW];    // fp16 NHWC
__device__ __align__(16) __half g_Ah [64*HW];    // ping-pong fp16 buffers
__device__ __align__(16) __half g_Bh [64*HW];
__device__ __align__(16) __half g_G [(size_t)HW*256];
__device__ float g_b0eff[256];
__device__ __align__(16) __half g_w1h[65536];    // fp16 MLP weights, [N][K]
__device__ __align__(16) __half g_w2h[65536];
__device__ __align__(16) __half g_w3h[65536];
__device__ __align__(16) __half g_wch[33*36864]; // fp16 conv weights [cv][tap][n][ic]
__device__ __align__(16) __half g_wl0[4*36864];  // fp16 layer-0 conv weights
__device__ unsigned g_bar_cnt;
__device__ volatile unsigned g_bar_gen;
__device__ int g_row_flag[128];

// ------------------------------ PTX helpers --------------------------------
__device__ __forceinline__ uint32_t smem_u32(const void* p) {
    uint32_t a;
    asm("{ .reg .u64 t; cvta.to.shared.u64 t, %1; cvt.u32.u64 %0, t; }"
        : "=r"(a) : "l"(p));
    return a;
}
__device__ __forceinline__ void cp_async16(uint32_t dst, const void* src) {
    asm volatile("cp.async.ca.shared.global [%0], [%1], 16;"
                 :: "r"(dst), "l"(src) : "memory");
}
__device__ __forceinline__ void cp_async16_cg(uint32_t dst, const void* src) {
    asm volatile("cp.async.cg.shared.global [%0], [%1], 16;"
                 :: "r"(dst), "l"(src) : "memory");
}
__device__ __forceinline__ void cp_commit() {
    asm volatile("cp.async.commit_group;" ::: "memory");
}
template<int N> __device__ __forceinline__ void cp_wait() {
    asm volatile("cp.async.wait_group %0;" :: "n"(N) : "memory");
}
// m16n8k16 f16 MMA, A row-major, B col-major, f32 accumulate (in-place)
__device__ __forceinline__ void mma16(float* d,
                                      uint32_t a0, uint32_t a1, uint32_t a2, uint32_t a3,
                                      uint32_t b0, uint32_t b1) {
    asm volatile(
        "mma.sync.aligned.m16n8k16.row.col.f32.f16.f16.f32 "
        "{%0,%1,%2,%3},{%4,%5,%6,%7},{%8,%9},{%0,%1,%2,%3};"
        : "+f"(d[0]), "+f"(d[1]), "+f"(d[2]), "+f"(d[3])
        : "r"(a0), "r"(a1), "r"(a2), "r"(a3), "r"(b0), "r"(b1));
}
// ldmatrix x4 (b16, non-transposed)
__device__ __forceinline__ void ldsm4(uint32_t& r0, uint32_t& r1,
                                      uint32_t& r2, uint32_t& r3, uint32_t addr) {
    asm volatile("ldmatrix.sync.aligned.m8n8.x4.shared.b16 {%0,%1,%2,%3}, [%4];"
                 : "=r"(r0), "=r"(r1), "=r"(r2), "=r"(r3) : "r"(addr));
}

// software grid barrier (all 128 CTAs resident; generation-based = replay-safe)
__device__ __forceinline__ void grid_barrier() {
    __syncthreads();
    if (threadIdx.x == 0) {
        __threadfence();
        unsigned gen = g_bar_gen;
        if (atomicAdd(&g_bar_cnt, 1u) == 127u) {
            atomicExch(&g_bar_cnt, 0u);
            __threadfence();
            g_bar_gen = gen + 1u;
        } else {
            while (g_bar_gen == gen) {}
        }
        __threadfence();
    }
    __syncthreads();
}

// ------------------------------ head conv (IC=3), NCHW in -> NHWC out -------
#define CTX 32
#define CTY 4
__global__ void conv_head(const float* __restrict__ x,
                          const float* __restrict__ w,
                          const float* __restrict__ bias,
                          float* __restrict__ out,
                          __half* __restrict__ outh)
{
    __shared__ float in_s[3][CTY+2][CTX+2];
    __shared__ float w_s[3*9*16];
    const int tx = threadIdx.x, ty = threadIdx.y;
    const int tid = ty*CTX + tx;
    const int x0 = blockIdx.x*CTX, y0 = blockIdx.y*CTY;
    const int ocg0 = blockIdx.z*16;

    float acc[16];
#pragma unroll
    for (int i = 0; i < 16; i++) acc[i] = 0.f;

    const int tot = 3*(CTY+2)*(CTX+2);
    for (int i = tid; i < tot; i += CTX*CTY) {
        int ic  = i / ((CTY+2)*(CTX+2));
        int rem = i % ((CTY+2)*(CTX+2));
        int ly = rem / (CTX+2), lx = rem % (CTX+2);
        int gy = y0 - 1 + ly, gx = x0 - 1 + lx;
        float v = 0.f;
        if (gy >= 0 && gy < H && gx >= 0 && gx < W)
            v = x[(size_t)ic*HW + gy*W + gx];
        in_s[ic][ly][lx] = v;
    }
    for (int i = tid; i < 3*9*16; i += CTX*CTY) {
        int oc = i & 15;
        int t2 = i >> 4;
        int tap = t2 % 9, ic = t2 / 9;
        w_s[(ic*9+tap)*16 + oc] = w[(size_t)(ocg0+oc)*27 + ic*9 + tap];
    }
    __syncthreads();
    for (int ic = 0; ic < 3; ic++) {
#pragma unroll
        for (int tap = 0; tap < 9; tap++) {
            const int dy = tap/3, dx = tap%3;
            float a = in_s[ic][ty+dy][tx+dx];
            const float4* wp = (const float4*)&w_s[(ic*9+tap)*16];
            float wv[16];
            *(float4*)&wv[0]  = wp[0];
            *(float4*)&wv[4]  = wp[1];
            *(float4*)&wv[8]  = wp[2];
            *(float4*)&wv[12] = wp[3];
#pragma unroll
            for (int oc = 0; oc < 16; oc++)
                acc[oc] = fmaf(a, wv[oc], acc[oc]);
        }
    }
    const int pix = (y0+ty)*W + (x0+tx);
    float4* o4 = (float4*)(out + (size_t)pix*64 + ocg0);
    __half2* oh2 = (__half2*)(outh + (size_t)pix*64 + ocg0);
#pragma unroll
    for (int v = 0; v < 4; v++) {
        float4 r;
        r.x = acc[v*4+0] + bias[ocg0+v*4+0];
        r.y = acc[v*4+1] + bias[ocg0+v*4+1];
        r.z = acc[v*4+2] + bias[ocg0+v*4+2];
        r.w = acc[v*4+3] + bias[ocg0+v*4+3];
        o4[v] = r;
        oh2[v*2]   = __floats2half2_rn(r.x, r.y);
        oh2[v*2+1] = __floats2half2_rn(r.z, r.w);
    }
}

// ------------------------------ merged weight transforms --------------------
#define N_WCH (33*36864)
#define N_WL0 (4*36864)
#define N_W123 (3*65536)
#define PREP_TOTAL (N_WCH + N_WL0 + N_W123 + 256)

__global__ void prep_all(const float* __restrict__ rb_w,
                         const float* __restrict__ tail_w,
                         const float* __restrict__ mw0,
                         const float* __restrict__ mb0,
                         const float* __restrict__ mw1,
                         const float* __restrict__ mw2,
                         const float* __restrict__ mw3,
                         __half* __restrict__ wch,
                         __half* __restrict__ wl0,
                         __half* __restrict__ wh1,
                         __half* __restrict__ wh2,
                         __half* __restrict__ wh3,
                         float* __restrict__ b0eff)
{
    int i = blockIdx.x*256 + threadIdx.x;
    if (i < N_WCH) {
        int cv = i / 36864;
        int r  = i % 36864;
        int tap = r >> 12;
        int r2  = r & 4095;
        int n   = r2 >> 6;
        int ic  = r2 & 63;
        const float* src = (cv < 32) ? (rb_w + (size_t)cv*36864) : tail_w;
        wch[i] = __float2half(src[(size_t)n*576 + ic*9 + tap]);
        return;
    }
    i -= N_WCH;
    if (i < N_WL0) {
        int grp = i / 36864;
        int r  = i % 36864;
        int tap = r >> 12;
        int r2  = r & 4095;
        int n   = r2 >> 6;
        int ic  = r2 & 63;
        int ng = grp*64 + n;
        wl0[i] = __float2half(mw0[(size_t)(ic*9 + tap)*256 + ng]);
        return;
    }
    i -= N_WL0;
    if (i < N_W123) {
        int which = i >> 16;
        int idx = i & 65535;
        int n = idx >> 8, k = idx & 255;
        const float* w = (which == 0) ? mw1 : (which == 1) ? mw2 : mw3;
        __half* wh = (which == 0) ? wh1 : (which == 1) ? wh2 : wh3;
        wh[idx] = __float2half(w[k*256 + n]);
        return;
    }
    i -= N_W123;
    if (i < 256)
        b0eff[i] = mb0[i] + 0.5f*mw0[578*256 + i] + 0.5f*mw0[579*256 + i];
}

// ------------------------------ fused persistent conv chain -----------------
// 128 CTAs, one per image row, neighbor-flag synchronized.
#define PXW 36
#define STRIPW2 (3*130*PXW)              // 14040 words
#define WTW (9*64*PXW)                   // 20736 words
#define RSW 68
#define OFF_RES (STRIPW2 + WTW)
#define OFF_H0  (OFF_RES + 128*RSW)
#define FSM_WORDS (OFF_H0 + 128*RSW)
#define FSMEM (FSM_WORDS*4)              // 208736 bytes

__global__ void __launch_bounds__(256) fused_conv(
    const __half* __restrict__ h0h, const float* __restrict__ h0f,
    const __half* __restrict__ wch, const float* __restrict__ rb_b,
    const float* __restrict__ tail_b, const __half* __restrict__ wl0,
    __half* __restrict__ bufA, __half* __restrict__ bufB,
    __half* __restrict__ G)
{
    extern __shared__ uint32_t sm[];
    uint32_t* strip = sm;
    uint32_t* wsm   = sm + STRIPW2;
    float* res_s = (float*)(sm + OFF_RES);
    float* h0_s  = (float*)(sm + OFF_H0);
    __shared__ float bias_s[64];

    const int tid = threadIdx.x, wid = tid >> 5, lane = tid & 31;
    const int g = lane >> 2, t = lane & 3;
    const int y = blockIdx.x;
    const uint32_t smaddr  = smem_u32(sm);
    const uint32_t wbase   = smaddr + STRIPW2*4;
    const uint32_t resaddr = smaddr + OFF_RES*4;
    const uint32_t h0addr  = smaddr + OFF_H0*4;

    {
        uint4 z = {0, 0, 0, 0};
        uint4* s4 = (uint4*)sm;
        for (int i = tid; i < STRIPW2/4; i += 256) s4[i] = z;
    }
    __syncthreads();

    for (int i = tid; i < 3120; i += 256) {
        int r = i / 1040, rem = i - r*1040;
        int j = rem >> 3, c = rem & 7;
        int gy = y - 1 + r, gx = j - 1;
        if (gy >= 0 && gy < H && gx >= 0 && gx < W)
            cp_async16(smaddr + (uint32_t)((r*130 + j)*PXW + c*4)*4,
                       h0h + ((size_t)(gy*W + gx))*64 + c*8);
    }
    for (int i = tid; i < 2048; i += 256) {
        int px = i >> 4, c = i & 15;
        const float* src = h0f + ((size_t)(y*W + px))*64 + c*4;
        cp_async16(resaddr + (uint32_t)(px*RSW + c*4)*4, src);
        cp_async16(h0addr  + (uint32_t)(px*RSW + c*4)*4, src);
    }
    for (int i = tid; i < 4608; i += 256) {
        int n2 = i >> 3, j = i & 7;
        cp_async16(wbase + (uint32_t)(n2*PXW + j*4)*4, wch + n2*64 + j*8);
    }
    cp_commit();

    if (tid == 0) g_row_flag[y] = 0;
    grid_barrier();

    cp_wait<0>();
    __syncthreads();

    const int m0 = (wid & 3)*32, n0 = (wid >> 2)*32;
    __half* bufs[2] = {bufA, bufB};

    for (int l = 0; l < 33; l++) {
        if (tid < 64) bias_s[tid] = (l < 32) ? rb_b[l*64 + tid] : tail_b[tid];

        float acc[2][4][4];
#pragma unroll
        for (int a = 0; a < 2; a++)
#pragma unroll
            for (int b = 0; b < 4; b++)
#pragma unroll
                for (int c = 0; c < 4; c++) acc[a][b][c] = 0.f;

        for (int tap = 0; tap < 9; tap++) {
            const int dy = tap/3, dx = tap%3;
            const uint32_t* wb = wsm + tap*(64*PXW);
            const uint32_t* arow0 = strip + (uint32_t)(dy*130 + dx)*PXW;
#pragma unroll
            for (int ks = 0; ks < 4; ks++) {
                const int kw = ks*8 + t;
                uint32_t af[2][4];
#pragma unroll
                for (int mt = 0; mt < 2; mt++) {
                    const uint32_t* ar = arow0 + (uint32_t)(m0 + mt*16 + g)*PXW + kw;
                    af[mt][0] = ar[0];
                    af[mt][1] = ar[8*PXW];
                    af[mt][2] = ar[4];
                    af[mt][3] = ar[8*PXW + 4];
                }
#pragma unroll
                for (int nt = 0; nt < 4; nt++) {
                    const uint32_t* bw = wb + (uint32_t)(n0 + nt*8 + g)*PXW + kw;
                    uint32_t b0 = bw[0], b1 = bw[4];
                    mma16(acc[0][nt], af[0][0], af[0][1], af[0][2], af[0][3], b0, b1);
                    mma16(acc[1][nt], af[1][0], af[1][1], af[1][2], af[1][3], b0, b1);
                }
            }
        }
        __syncthreads();

        const __half* wnext = (l < 32) ? (wch + (size_t)(l + 1)*36864) : wl0;
        for (int i = tid; i < 4608; i += 256) {
            int n2 = i >> 3, j = i & 7;
            cp_async16(wbase + (uint32_t)(n2*PXW + j*4)*4, wnext + n2*64 + j*8);
        }
        cp_commit();

        __half* outb = bufs[l & 1];
        const int mode = (l == 32) ? 2 : (l & 1);
#pragma unroll
        for (int mt = 0; mt < 2; mt++) {
            const int p1 = m0 + mt*16 + g;
            const int p2 = p1 + 8;
#pragma unroll
            for (int nt = 0; nt < 4; nt++) {
                const int c0 = n0 + nt*8 + 2*t;
                float v0 = acc[mt][nt][0], v1 = acc[mt][nt][1];
                float v2 = acc[mt][nt][2], v3 = acc[mt][nt][3];
                float b0 = bias_s[c0], b1 = bias_s[c0 + 1];
                if (mode == 0) {
                    v0 = fmaxf(v0 + b0, 0.f); v1 = fmaxf(v1 + b1, 0.f);
                    v2 = fmaxf(v2 + b0, 0.f); v3 = fmaxf(v3 + b1, 0.f);
                } else if (mode == 1) {
                    float2 r0 = *(const float2*)(res_s + p1*RSW + c0);
                    float2 r1 = *(const float2*)(res_s + p2*RSW + c0);
                    v0 += b0 + r0.x; v1 += b1 + r0.y;
                    v2 += b0 + r1.x; v3 += b1 + r1.y;
                    float2 s0 = {v0, v1}, s1 = {v2, v3};
                    *(float2*)(res_s + p1*RSW + c0) = s0;
                    *(float2*)(res_s + p2*RSW + c0) = s1;
                } else {
                    float2 r0 = *(const float2*)(h0_s + p1*RSW + c0);
                    float2 r1 = *(const float2*)(h0_s + p2*RSW + c0);
                    v0 += b0 + r0.x; v1 += b1 + r0.y;
                    v2 += b0 + r1.x; v3 += b1 + r1.y;
                }
                __half2 h0v = __floats2half2_rn(v0, v1);
                __half2 h1v = __floats2half2_rn(v2, v3);
                *(__half2*)(outb + ((size_t)(y*W + p1))*64 + c0) = h0v;
                *(__half2*)(outb + ((size_t)(y*W + p2))*64 + c0) = h1v;
                const int cw = (c0 >> 1);
                strip[(uint32_t)(130 + 1 + p1)*PXW + cw] = *(const uint32_t*)&h0v;
                strip[(uint32_t)(130 + 1 + p2)*PXW + cw] = *(const uint32_t*)&h1v;
            }
        }
        __threadfence();
        __syncthreads();
        if (tid == 0) {
            atomicExch(&g_row_flag[y], l + 1);
            if (y > 0)
                while (*(volatile int*)&g_row_flag[y - 1] < l + 1) {}
            __threadfence();
        }
        if (tid == 32 && y < 127) {
            while (*(volatile int*)&g_row_flag[y + 1] < l + 1) {}
            __threadfence();
        }
        __syncthreads();

        for (int i = tid; i < 2080; i += 256) {
            int rr = i / 1040, rem = i - rr*1040;
            int j = rem >> 3, c = rem & 7;
            int r = rr*2;
            int gy = y - 1 + r, gx = j - 1;
            if (gy >= 0 && gy < H && gx >= 0 && gx < W)
                cp_async16_cg(smaddr + (uint32_t)((r*130 + j)*PXW + c*4)*4,
                              outb + ((size_t)(gy*W + gx))*64 + c*8);
        }
        cp_commit();
        cp_wait<0>();
        __syncthreads();
    }

    for (int grp = 0; grp < 4; grp++) {
        float acc[2][4][4];
#pragma unroll
        for (int a = 0; a < 2; a++)
#pragma unroll
            for (int b = 0; b < 4; b++)
#pragma unroll
                for (int c = 0; c < 4; c++) acc[a][b][c] = 0.f;

        for (int tap = 0; tap < 9; tap++) {
            const int dy = tap/3, dx = tap%3;
            const uint32_t* wb = wsm + tap*(64*PXW);
            const uint32_t* arow0 = strip + (uint32_t)(dy*130 + dx)*PXW;
#pragma unroll
            for (int ks = 0; ks < 4; ks++) {
                const int kw = ks*8 + t;
                uint32_t af[2][4];
#pragma unroll
                for (int mt = 0; mt < 2; mt++) {
                    const uint32_t* ar = arow0 + (uint32_t)(m0 + mt*16 + g)*PXW + kw;
                    af[mt][0] = ar[0];
                    af[mt][1] = ar[8*PXW];
                    af[mt][2] = ar[4];
                    af[mt][3] = ar[8*PXW + 4];
                }
#pragma unroll
                for (int nt = 0; nt < 4; nt++) {
                    const uint32_t* bw = wb + (uint32_t)(n0 + nt*8 + g)*PXW + kw;
                    uint32_t b0 = bw[0], b1 = bw[4];
                    mma16(acc[0][nt], af[0][0], af[0][1], af[0][2], af[0][3], b0, b1);
                    mma16(acc[1][nt], af[1][0], af[1][1], af[1][2], af[1][3], b0, b1);
                }
            }
        }
        __syncthreads();

        if (grp < 3) {
            const __half* wnext = wl0 + (size_t)(grp + 1)*36864;
            for (int i = tid; i < 4608; i += 256) {
                int n2 = i >> 3, j = i & 7;
                cp_async16(wbase + (uint32_t)(n2*PXW + j*4)*4, wnext + n2*64 + j*8);
            }
            cp_commit();
        }

#pragma unroll
        for (int mt = 0; mt < 2; mt++) {
            const int p1 = m0 + mt*16 + g;
            const int p2 = p1 + 8;
#pragma unroll
            for (int nt = 0; nt < 4; nt++) {
                const int c0 = n0 + nt*8 + 2*t;
                const int cc = grp*64 + c0;
                __half2 h0v = __floats2half2_rn(acc[mt][nt][0], acc[mt][nt][1]);
                __half2 h1v = __floats2half2_rn(acc[mt][nt][2], acc[mt][nt][3]);
                *(__half2*)(G + ((size_t)(y*W + p1))*256 + cc) = h0v;
                *(__half2*)(G + ((size_t)(y*W + p2))*256 + cc) = h1v;
            }
        }
        if (grp < 3) {
            cp_wait<0>();
            __syncthreads();
        }
    }
}

// ------------------------------ LIIF query + mma.sync fp16 MLP --------------
// 256 threads / 8 warps: 4 M-groups x 2 N-groups; fragments via ldmatrix.
#define QB 32
#define SB 128
#define QTHREADS 256
#define ASH 264
#define WSH 72
#define OFF_ACT 0
#define OFF_WB0 67584
#define OFF_WB1 104448
#define OFF_BIAS 141312
#define DYN_BYTES 142336

__device__ __forceinline__ void load_wchunk(uint32_t dst_base,
                                            const __half* __restrict__ Wg,
                                            int c, int tid)
{
#pragma unroll
    for (int ii = 0; ii < 8; ii++) {
        int i = tid + ii*QTHREADS;
        int n = i >> 3, j = i & 7;
        cp_async16(dst_base + (uint32_t)(n*(WSH*2) + j*16),
                   Wg + (size_t)n*256 + c*64 + j*8);
    }
}

__global__ __launch_bounds__(QTHREADS)
void query_kernel(const __half* __restrict__ G,
                  const float* __restrict__ mw0,
                  const float* __restrict__ b0eff,
                  const __half* __restrict__ w1h, const float* __restrict__ b1,
                  const __half* __restrict__ w2h, const float* __restrict__ b2,
                  const __half* __restrict__ w3h, const float* __restrict__ b3,
                  const float* __restrict__ w4, const float* __restrict__ b4,
                  float* __restrict__ out)
{
    extern __shared__ char dyn[];
    uint32_t* actu = (uint32_t*)(dyn + OFF_ACT);
    __half*   acth = (__half*)(dyn + OFF_ACT);
    float*    bias_s = (float*)(dyn + OFF_BIAS);
    __shared__ int   p_s[SB];
    __shared__ float relh_s[SB], relw_s[SB], area_s[SB];
    __shared__ float pred_s[SB][4];

    const int tid  = threadIdx.x;
    const int wid  = tid >> 5;
    const int lane = tid & 31;
    const int g    = lane >> 2;
    const int t    = lane & 3;
    const int mi   = lane >> 3;      // ldmatrix matrix index
    const int rr   = lane & 7;       // ldmatrix row within matrix

    const uint32_t dynaddr = smem_u32(dyn);
    const uint32_t wbaddr[2] = {dynaddr + OFF_WB0, dynaddr + OFF_WB1};

    if (tid < SB) {
        int m  = tid;
        int q  = blockIdx.x*QB + (m >> 2);
        int oh = q >> 9, ow = q & 511;
        int r  = (m >> 1) & 1, c = m & 1;
        float sh = (oh + 0.5f)*(2.0f/512.0f) - 1.0f;
        float sw = (ow + 0.5f)*(2.0f/512.0f) - 1.0f;
        const float d = 1.0f/128.0f, EPS = 1e-6f;
        float gh = fminf(fmaxf(sh + (2.f*r - 1.f)*d, -1.f + EPS), 1.f - EPS);
        float gw = fminf(fmaxf(sw + (2.f*c - 1.f)*d, -1.f + EPS), 1.f - EPS);
        float fy = ((gh + 1.0f)*128.0f - 1.0f)*0.5f;
        float fx = ((gw + 1.0f)*128.0f - 1.0f)*0.5f;
        int iy = min(max((int)rintf(fy), 0), 127);
        int ix = min(max((int)rintf(fx), 0), 127);
        float qgh = (iy + 0.5f)*(2.0f/128.0f) - 1.0f;
        float qgw = (ix + 0.5f)*(2.0f/128.0f) - 1.0f;
        float rh = (sh - qgh)*128.0f;
        float rw = (sw - qgw)*128.0f;
        p_s[m] = iy*128 + ix;
        relh_s[m] = rh; relw_s[m] = rw;
        area_s[m] = fabsf(rh*rw);
    }

    load_wchunk(wbaddr[0], w1h, 0, tid);
    cp_commit();
    __syncthreads();

    // ---- stage 1: A0 = relu(G[p] + rel_h*U + rel_w*V + b0eff) -> fp16
    {
        const int ocw = tid & 127;
        const int oc0 = ocw*2;
        float u0 = mw0[576*256 + oc0],     u1 = mw0[576*256 + oc0 + 1];
        float v0 = mw0[577*256 + oc0],     v1 = mw0[577*256 + oc0 + 1];
        float b0v = b0eff[oc0],            b1v = b0eff[oc0 + 1];
        const __half2* G2 = (const __half2*)G;
        for (int m = (tid >> 7); m < SB; m += 2) {
            __half2 gg = G2[(size_t)p_s[m]*128 + ocw];
            float rh = relh_s[m], rw = relw_s[m];
            float x0v = fmaf(rh, u0, fmaf(rw, v0, __low2float(gg)  + b0v));
            float x1v = fmaf(rh, u1, fmaf(rw, v1, __high2float(gg) + b1v));
            __half2 hv = __floats2half2_rn(fmaxf(x0v, 0.f), fmaxf(x1v, 0.f));
            actu[m*(ASH/2) + ocw] = *(const uint32_t*)&hv;
        }
    }
    __syncthreads();

    const int m0  = (wid & 3)*32;
    const int n0b = (wid >> 2)*128;

    // ---- ldmatrix lane addresses (bytes)
    // A mt-tile: matrices [m-lo/k-lo, m-hi/k-lo, m-lo/k-hi, m-hi/k-hi]
    uint32_t aAddr[2];
#pragma unroll
    for (int mt = 0; mt < 2; mt++) {
        int row = m0 + mt*16 + (mi & 1)*8 + rr;
        aAddr[mt] = dynaddr + OFF_ACT
                  + (uint32_t)(row*(ASH/2) + (mi >> 1)*4)*4u;
    }
    // B nt-pair p: matrices [nt/k-lo, nt/k-hi, nt+1/k-lo, nt+1/k-hi]
    uint32_t bOff[8];
#pragma unroll
    for (int p = 0; p < 8; p++) {
        int row = n0b + (2*p + (mi >> 1))*8 + rr;
        bOff[p] = (uint32_t)(row*(WSH/2) + (mi & 1)*4)*4u;
    }

    const __half* Ws[3] = {w1h, w2h, w3h};
    const float*  Bs[3] = {b1, b2, b3};

    int cnt = 0;
    for (int L = 0; L < 3; L++) {
        bias_s[tid] = Bs[L][tid];

        float acc[2][16][4];
#pragma unroll
        for (int mt = 0; mt < 2; mt++)
#pragma unroll
            for (int nt = 0; nt < 16; nt++)
#pragma unroll
                for (int i = 0; i < 4; i++) acc[mt][nt][i] = 0.f;

        for (int c = 0; c < 4; c++) {
            const bool has_next = (c < 3) || (L < 2);
            if (has_next) {
                const __half* Wn = (c < 3) ? Ws[L] : Ws[L+1];
                const int cn = (c < 3) ? c + 1 : 0;
                load_wchunk(wbaddr[(cnt + 1) & 1], Wn, cn, tid);
                cp_commit();
                cp_wait<1>();
            } else {
                cp_wait<0>();
            }
            __syncthreads();

            const uint32_t wbA = wbaddr[cnt & 1];
#pragma unroll
            for (int ks = 0; ks < 4; ks++) {
                const uint32_t kbyte = (uint32_t)(c*32 + ks*8)*4u;
                uint32_t af[2][4];
                ldsm4(af[0][0], af[0][1], af[0][2], af[0][3], aAddr[0] + kbyte);
                ldsm4(af[1][0], af[1][1], af[1][2], af[1][3], aAddr[1] + kbyte);
                const uint32_t kb = (uint32_t)(ks*8)*4u;
#pragma unroll
                for (int p = 0; p < 8; p++) {
                    uint32_t b0a, b1a, b0b, b1b;
                    ldsm4(b0a, b1a, b0b, b1b, wbA + bOff[p] + kb);
                    mma16(acc[0][2*p],   af[0][0], af[0][1], af[0][2], af[0][3], b0a, b1a);
                    mma16(acc[1][2*p],   af[1][0], af[1][1], af[1][2], af[1][3], b0a, b1a);
                    mma16(acc[0][2*p+1], af[0][0], af[0][1], af[0][2], af[0][3], b0b, b1b);
                    mma16(acc[1][2*p+1], af[1][0], af[1][1], af[1][2], af[1][3], b0b, b1b);
                }
            }
            cnt++;
            __syncthreads();
        }

#pragma unroll
        for (int mt = 0; mt < 2; mt++) {
            const int r0 = m0 + mt*16 + g;
#pragma unroll
            for (int nt = 0; nt < 16; nt++) {
                const int col = n0b + nt*8 + 2*t;
                float v0 = fmaxf(acc[mt][nt][0] + bias_s[col],     0.f);
                float v1 = fmaxf(acc[mt][nt][1] + bias_s[col + 1], 0.f);
                float v2 = fmaxf(acc[mt][nt][2] + bias_s[col],     0.f);
                float v3 = fmaxf(acc[mt][nt][3] + bias_s[col + 1], 0.f);
                __half2 h01 = __floats2half2_rn(v0, v1);
                __half2 h23 = __floats2half2_rn(v2, v3);
                const int cw = (n0b >> 1) + nt*4 + t;
                actu[r0*(ASH/2) + cw]     = *(const uint32_t*)&h01;
                actu[(r0+8)*(ASH/2) + cw] = *(const uint32_t*)&h23;
            }
        }
        __syncthreads();
    }

    // ---- stage 3: output layer 256->3 (fp32 accumulate over fp16 acts)
    {
        float* wsm = (float*)(dyn + OFF_WB0);
        for (int i = tid; i < 768; i += QTHREADS) wsm[i] = w4[i];
        __syncthreads();
        if (tid < SB) {
            const __half* ap = acth + tid*ASH;
            float s0 = b4[0], s1 = b4[1], s2 = b4[2];
#pragma unroll 4
            for (int k = 0; k < 256; k++) {
                float a = __half2float(ap[k]);
                s0 = fmaf(a, wsm[k*3 + 0], s0);
                s1 = fmaf(a, wsm[k*3 + 1], s1);
                s2 = fmaf(a, wsm[k*3 + 2], s2);
            }
            pred_s[tid][0] = s0; pred_s[tid][1] = s1; pred_s[tid][2] = s2;
        }
    }
    __syncthreads();

    if (tid < QB) {
        int bb = tid*4;
        float a0 = area_s[bb+0], a1 = area_s[bb+1];
        float a2 = area_s[bb+2], a3 = area_s[bb+3];
        float tot = a0 + a1 + a2 + a3 + 1e-9f;
        int q = blockIdx.x*QB + tid;
#pragma unroll
        for (int j = 0; j < 3; j++) {
            float num = pred_s[bb+0][j]*a3 + pred_s[bb+1][j]*a2
                      + pred_s[bb+2][j]*a1 + pred_s[bb+3][j]*a0;
            float yv = num / tot;
            yv = fminf(fmaxf(yv, 0.f), 1.f);
            out[(size_t)j*NQ + q] = yv;
        }
    }
}

// ------------------------------ launch --------------------------------------
extern "C" void kernel_launch(void* const* d_in, const int* in_sizes, int n_in,
                              void* d_out, int out_size)
{
    const float* x      = (const float*)d_in[0];
    const float* head_w = (const float*)d_in[2];
    const float* head_b = (const float*)d_in[3];
    const float* rb_w   = (const float*)d_in[4];
    const float* rb_b   = (const float*)d_in[5];
    const float* tail_w = (const float*)d_in[6];
    const float* tail_b = (const float*)d_in[7];
    const float* mw0 = (const float*)d_in[8];
    const float* mb0 = (const float*)d_in[9];
    const float* mw1 = (const float*)d_in[10];
    const float* mb1 = (const float*)d_in[11];
    const float* mw2 = (const float*)d_in[12];
    const float* mb2 = (const float*)d_in[13];
    const float* mw3 = (const float*)d_in[14];
    const float* mb3 = (const float*)d_in[15];
    const float* mw4 = (const float*)d_in[16];
    const float* mb4 = (const float*)d_in[17];
    float* out = (float*)d_out;

    float *h0, *b0eff;
    __half *h0h, *Ah, *Bh, *G, *w1h, *w2h, *w3h, *wch, *wl0;
    cudaGetSymbolAddress((void**)&h0, g_h0);
    cudaGetSymbolAddress((void**)&h0h, g_h0h);
    cudaGetSymbolAddress((void**)&Ah,  g_Ah);
    cudaGetSymbolAddress((void**)&Bh,  g_Bh);
    cudaGetSymbolAddress((void**)&G,  g_G);
    cudaGetSymbolAddress((void**)&b0eff, g_b0eff);
    cudaGetSymbolAddress((void**)&w1h, g_w1h);
    cudaGetSymbolAddress((void**)&w2h, g_w2h);
    cudaGetSymbolAddress((void**)&w3h, g_w3h);
    cudaGetSymbolAddress((void**)&wch, g_wch);
    cudaGetSymbolAddress((void**)&wl0, g_wl0);

    prep_all<<<(PREP_TOTAL + 255)/256, 256>>>(rb_w, tail_w, mw0, mb0,
                                              mw1, mw2, mw3,
                                              wch, wl0, w1h, w2h, w3h, b0eff);

    conv_head<<<dim3(W/CTX, H/CTY, 4), dim3(CTX, CTY)>>>(x, head_w, head_b,
                                                         h0, h0h);

    cudaFuncSetAttribute(fused_conv,
                         cudaFuncAttributeMaxDynamicSharedMemorySize, FSMEM);
    fused_conv<<<128, 256, FSMEM>>>(h0h, h0, wch, rb_b, tail_b, wl0,
                                    Ah, Bh, G);

    cudaFuncSetAttribute(query_kernel,
                         cudaFuncAttributeMaxDynamicSharedMemorySize,
                         DYN_BYTES);
    query_kernel<<<NQ/QB, QTHREADS, DYN_BYTES>>>(
        G, mw0, b0eff, w1h, mb1, w2h, mb2, w3h, mb3, mw4, mb4, out);
}

// round 14
// speedup vs baseline: 1.0801x; 1.0801x over previous
#include <cuda_runtime.h>
#include <cuda_fp16.h>
#include <cstdint>

#define H 128
#define W 128
#define HW 16384
#define OH 512
#define OWID 512
#define NQ (OH*OWID)

// ------------------------------ scratch (device globals, no allocation) ----
__device__ __align__(16) float g_h0[64*HW];      // fp32 NHWC (head conv out)
__device__ __align__(16) __half g_h0h[64*HW];    // fp16 NHWC
__device__ __align__(16) __half g_Ah [64*HW];    // ping-pong fp16 buffers
__device__ __align__(16) __half g_Bh [64*HW];
__device__ __align__(16) __half g_G [(size_t)HW*256];
__device__ float g_b0eff[256];
__device__ __align__(16) __half g_w1h[65536];    // fp16 MLP weights, [N][K]
__device__ __align__(16) __half g_w2h[65536];
__device__ __align__(16) __half g_w3h[65536];
__device__ __align__(16) __half g_wch[33*36864]; // fp16 conv weights [cv][tap][n][ic]
__device__ __align__(16) __half g_wl0[4*36864];  // fp16 layer-0 conv weights
__device__ unsigned g_bar_cnt;
__device__ volatile unsigned g_bar_gen;
__device__ int g_row_flag[128];

// ------------------------------ PTX helpers --------------------------------
__device__ __forceinline__ uint32_t smem_u32(const void* p) {
    uint32_t a;
    asm("{ .reg .u64 t; cvta.to.shared.u64 t, %1; cvt.u32.u64 %0, t; }"
        : "=r"(a) : "l"(p));
    return a;
}
__device__ __forceinline__ void cp_async16(uint32_t dst, const void* src) {
    asm volatile("cp.async.ca.shared.global [%0], [%1], 16;"
                 :: "r"(dst), "l"(src) : "memory");
}
__device__ __forceinline__ void cp_async16_cg(uint32_t dst, const void* src) {
    asm volatile("cp.async.cg.shared.global [%0], [%1], 16;"
                 :: "r"(dst), "l"(src) : "memory");
}
__device__ __forceinline__ void cp_commit() {
    asm volatile("cp.async.commit_group;" ::: "memory");
}
template<int N> __device__ __forceinline__ void cp_wait() {
    asm volatile("cp.async.wait_group %0;" :: "n"(N) : "memory");
}
// m16n8k16 f16 MMA, A row-major, B col-major, f32 accumulate (in-place)
__device__ __forceinline__ void mma16(float* d,
                                      uint32_t a0, uint32_t a1, uint32_t a2, uint32_t a3,
                                      uint32_t b0, uint32_t b1) {
    asm volatile(
        "mma.sync.aligned.m16n8k16.row.col.f32.f16.f16.f32 "
        "{%0,%1,%2,%3},{%4,%5,%6,%7},{%8,%9},{%0,%1,%2,%3};"
        : "+f"(d[0]), "+f"(d[1]), "+f"(d[2]), "+f"(d[3])
        : "r"(a0), "r"(a1), "r"(a2), "r"(a3), "r"(b0), "r"(b1));
}
// ldmatrix x4 (b16, non-transposed)
__device__ __forceinline__ void ldsm4(uint32_t& r0, uint32_t& r1,
                                      uint32_t& r2, uint32_t& r3, uint32_t addr) {
    asm volatile("ldmatrix.sync.aligned.m8n8.x4.shared.b16 {%0,%1,%2,%3}, [%4];"
                 : "=r"(r0), "=r"(r1), "=r"(r2), "=r"(r3) : "r"(addr));
}

// software grid barrier (all 128 CTAs resident; generation-based = replay-safe)
__device__ __forceinline__ void grid_barrier() {
    __syncthreads();
    if (threadIdx.x == 0) {
        __threadfence();
        unsigned gen = g_bar_gen;
        if (atomicAdd(&g_bar_cnt, 1u) == 127u) {
            atomicExch(&g_bar_cnt, 0u);
            __threadfence();
            g_bar_gen = gen + 1u;
        } else {
            while (g_bar_gen == gen) {}
        }
        __threadfence();
    }
    __syncthreads();
}

// ------------------------------ head conv (IC=3), NCHW in -> NHWC out -------
#define CTX 32
#define CTY 4
__global__ void conv_head(const float* __restrict__ x,
                          const float* __restrict__ w,
                          const float* __restrict__ bias,
                          float* __restrict__ out,
                          __half* __restrict__ outh)
{
    __shared__ float in_s[3][CTY+2][CTX+2];
    __shared__ float w_s[3*9*16];
    const int tx = threadIdx.x, ty = threadIdx.y;
    const int tid = ty*CTX + tx;
    const int x0 = blockIdx.x*CTX, y0 = blockIdx.y*CTY;
    const int ocg0 = blockIdx.z*16;

    float acc[16];
#pragma unroll
    for (int i = 0; i < 16; i++) acc[i] = 0.f;

    const int tot = 3*(CTY+2)*(CTX+2);
    for (int i = tid; i < tot; i += CTX*CTY) {
        int ic  = i / ((CTY+2)*(CTX+2));
        int rem = i % ((CTY+2)*(CTX+2));
        int ly = rem / (CTX+2), lx = rem % (CTX+2);
        int gy = y0 - 1 + ly, gx = x0 - 1 + lx;
        float v = 0.f;
        if (gy >= 0 && gy < H && gx >= 0 && gx < W)
            v = x[(size_t)ic*HW + gy*W + gx];
        in_s[ic][ly][lx] = v;
    }
    for (int i = tid; i < 3*9*16; i += CTX*CTY) {
        int oc = i & 15;
        int t2 = i >> 4;
        int tap = t2 % 9, ic = t2 / 9;
        w_s[(ic*9+tap)*16 + oc] = w[(size_t)(ocg0+oc)*27 + ic*9 + tap];
    }
    __syncthreads();
    for (int ic = 0; ic < 3; ic++) {
#pragma unroll
        for (int tap = 0; tap < 9; tap++) {
            const int dy = tap/3, dx = tap%3;
            float a = in_s[ic][ty+dy][tx+dx];
            const float4* wp = (const float4*)&w_s[(ic*9+tap)*16];
            float wv[16];
            *(float4*)&wv[0]  = wp[0];
            *(float4*)&wv[4]  = wp[1];
            *(float4*)&wv[8]  = wp[2];
            *(float4*)&wv[12] = wp[3];
#pragma unroll
            for (int oc = 0; oc < 16; oc++)
                acc[oc] = fmaf(a, wv[oc], acc[oc]);
        }
    }
    const int pix = (y0+ty)*W + (x0+tx);
    float4* o4 = (float4*)(out + (size_t)pix*64 + ocg0);
    __half2* oh2 = (__half2*)(outh + (size_t)pix*64 + ocg0);
#pragma unroll
    for (int v = 0; v < 4; v++) {
        float4 r;
        r.x = acc[v*4+0] + bias[ocg0+v*4+0];
        r.y = acc[v*4+1] + bias[ocg0+v*4+1];
        r.z = acc[v*4+2] + bias[ocg0+v*4+2];
        r.w = acc[v*4+3] + bias[ocg0+v*4+3];
        o4[v] = r;
        oh2[v*2]   = __floats2half2_rn(r.x, r.y);
        oh2[v*2+1] = __floats2half2_rn(r.z, r.w);
    }
}

// ------------------------------ merged weight transforms --------------------
#define N_WCH (33*36864)
#define N_WL0 (4*36864)
#define N_W123 (3*65536)
#define PREP_TOTAL (N_WCH + N_WL0 + N_W123 + 256)

__global__ void prep_all(const float* __restrict__ rb_w,
                         const float* __restrict__ tail_w,
                         const float* __restrict__ mw0,
                         const float* __restrict__ mb0,
                         const float* __restrict__ mw1,
                         const float* __restrict__ mw2,
                         const float* __restrict__ mw3,
                         __half* __restrict__ wch,
                         __half* __restrict__ wl0,
                         __half* __restrict__ wh1,
                         __half* __restrict__ wh2,
                         __half* __restrict__ wh3,
                         float* __restrict__ b0eff)
{
    int i = blockIdx.x*256 + threadIdx.x;
    if (i < N_WCH) {
        int cv = i / 36864;
        int r  = i % 36864;
        int tap = r >> 12;
        int r2  = r & 4095;
        int n   = r2 >> 6;
        int ic  = r2 & 63;
        const float* src = (cv < 32) ? (rb_w + (size_t)cv*36864) : tail_w;
        wch[i] = __float2half(src[(size_t)n*576 + ic*9 + tap]);
        return;
    }
    i -= N_WCH;
    if (i < N_WL0) {
        int grp = i / 36864;
        int r  = i % 36864;
        int tap = r >> 12;
        int r2  = r & 4095;
        int n   = r2 >> 6;
        int ic  = r2 & 63;
        int ng = grp*64 + n;
        wl0[i] = __float2half(mw0[(size_t)(ic*9 + tap)*256 + ng]);
        return;
    }
    i -= N_WL0;
    if (i < N_W123) {
        int which = i >> 16;
        int idx = i & 65535;
        int n = idx >> 8, k = idx & 255;
        const float* w = (which == 0) ? mw1 : (which == 1) ? mw2 : mw3;
        __half* wh = (which == 0) ? wh1 : (which == 1) ? wh2 : wh3;
        wh[idx] = __float2half(w[k*256 + n]);
        return;
    }
    i -= N_W123;
    if (i < 256)
        b0eff[i] = mb0[i] + 0.5f*mw0[578*256 + i] + 0.5f*mw0[579*256 + i];
}

// ------------------------------ fused persistent conv chain -----------------
// 128 CTAs, one per image row, neighbor-flag synchronized.
#define PXW 36
#define STRIPW2 (3*130*PXW)              // 14040 words
#define WTW (9*64*PXW)                   // 20736 words
#define RSW 68
#define OFF_RES (STRIPW2 + WTW)
#define OFF_H0  (OFF_RES + 128*RSW)
#define FSM_WORDS (OFF_H0 + 128*RSW)
#define FSMEM (FSM_WORDS*4)              // 208736 bytes

__global__ void __launch_bounds__(256) fused_conv(
    const __half* __restrict__ h0h, const float* __restrict__ h0f,
    const __half* __restrict__ wch, const float* __restrict__ rb_b,
    const float* __restrict__ tail_b, const __half* __restrict__ wl0,
    __half* __restrict__ bufA, __half* __restrict__ bufB,
    __half* __restrict__ G)
{
    extern __shared__ uint32_t sm[];
    uint32_t* strip = sm;
    uint32_t* wsm   = sm + STRIPW2;
    float* res_s = (float*)(sm + OFF_RES);
    float* h0_s  = (float*)(sm + OFF_H0);
    __shared__ float bias_s[64];

    const int tid = threadIdx.x, wid = tid >> 5, lane = tid & 31;
    const int g = lane >> 2, t = lane & 3;
    const int y = blockIdx.x;
    const uint32_t smaddr  = smem_u32(sm);
    const uint32_t wbase   = smaddr + STRIPW2*4;
    const uint32_t resaddr = smaddr + OFF_RES*4;
    const uint32_t h0addr  = smaddr + OFF_H0*4;

    {
        uint4 z = {0, 0, 0, 0};
        uint4* s4 = (uint4*)sm;
        for (int i = tid; i < STRIPW2/4; i += 256) s4[i] = z;
    }
    __syncthreads();

    for (int i = tid; i < 3120; i += 256) {
        int r = i / 1040, rem = i - r*1040;
        int j = rem >> 3, c = rem & 7;
        int gy = y - 1 + r, gx = j - 1;
        if (gy >= 0 && gy < H && gx >= 0 && gx < W)
            cp_async16(smaddr + (uint32_t)((r*130 + j)*PXW + c*4)*4,
                       h0h + ((size_t)(gy*W + gx))*64 + c*8);
    }
    for (int i = tid; i < 2048; i += 256) {
        int px = i >> 4, c = i & 15;
        const float* src = h0f + ((size_t)(y*W + px))*64 + c*4;
        cp_async16(resaddr + (uint32_t)(px*RSW + c*4)*4, src);
        cp_async16(h0addr  + (uint32_t)(px*RSW + c*4)*4, src);
    }
    for (int i = tid; i < 4608; i += 256) {
        int n2 = i >> 3, j = i & 7;
        cp_async16(wbase + (uint32_t)(n2*PXW + j*4)*4, wch + n2*64 + j*8);
    }
    cp_commit();

    if (tid == 0) g_row_flag[y] = 0;
    grid_barrier();

    cp_wait<0>();
    __syncthreads();

    const int m0 = (wid & 3)*32, n0 = (wid >> 2)*32;
    __half* bufs[2] = {bufA, bufB};

    for (int l = 0; l < 33; l++) {
        if (tid < 64) bias_s[tid] = (l < 32) ? rb_b[l*64 + tid] : tail_b[tid];

        float acc[2][4][4];
#pragma unroll
        for (int a = 0; a < 2; a++)
#pragma unroll
            for (int b = 0; b < 4; b++)
#pragma unroll
                for (int c = 0; c < 4; c++) acc[a][b][c] = 0.f;

        for (int tap = 0; tap < 9; tap++) {
            const int dy = tap/3, dx = tap%3;
            const uint32_t* wb = wsm + tap*(64*PXW);
            const uint32_t* arow0 = strip + (uint32_t)(dy*130 + dx)*PXW;
#pragma unroll
            for (int ks = 0; ks < 4; ks++) {
                const int kw = ks*8 + t;
                uint32_t af[2][4];
#pragma unroll
                for (int mt = 0; mt < 2; mt++) {
                    const uint32_t* ar = arow0 + (uint32_t)(m0 + mt*16 + g)*PXW + kw;
                    af[mt][0] = ar[0];
                    af[mt][1] = ar[8*PXW];
                    af[mt][2] = ar[4];
                    af[mt][3] = ar[8*PXW + 4];
                }
#pragma unroll
                for (int nt = 0; nt < 4; nt++) {
                    const uint32_t* bw = wb + (uint32_t)(n0 + nt*8 + g)*PXW + kw;
                    uint32_t b0 = bw[0], b1 = bw[4];
                    mma16(acc[0][nt], af[0][0], af[0][1], af[0][2], af[0][3], b0, b1);
                    mma16(acc[1][nt], af[1][0], af[1][1], af[1][2], af[1][3], b0, b1);
                }
            }
        }
        __syncthreads();

        const __half* wnext = (l < 32) ? (wch + (size_t)(l + 1)*36864) : wl0;
        for (int i = tid; i < 4608; i += 256) {
            int n2 = i >> 3, j = i & 7;
            cp_async16(wbase + (uint32_t)(n2*PXW + j*4)*4, wnext + n2*64 + j*8);
        }
        cp_commit();

        __half* outb = bufs[l & 1];
        const int mode = (l == 32) ? 2 : (l & 1);
#pragma unroll
        for (int mt = 0; mt < 2; mt++) {
            const int p1 = m0 + mt*16 + g;
            const int p2 = p1 + 8;
#pragma unroll
            for (int nt = 0; nt < 4; nt++) {
                const int c0 = n0 + nt*8 + 2*t;
                float v0 = acc[mt][nt][0], v1 = acc[mt][nt][1];
                float v2 = acc[mt][nt][2], v3 = acc[mt][nt][3];
                float b0 = bias_s[c0], b1 = bias_s[c0 + 1];
                if (mode == 0) {
                    v0 = fmaxf(v0 + b0, 0.f); v1 = fmaxf(v1 + b1, 0.f);
                    v2 = fmaxf(v2 + b0, 0.f); v3 = fmaxf(v3 + b1, 0.f);
                } else if (mode == 1) {
                    float2 r0 = *(const float2*)(res_s + p1*RSW + c0);
                    float2 r1 = *(const float2*)(res_s + p2*RSW + c0);
                    v0 += b0 + r0.x; v1 += b1 + r0.y;
                    v2 += b0 + r1.x; v3 += b1 + r1.y;
                    float2 s0 = {v0, v1}, s1 = {v2, v3};
                    *(float2*)(res_s + p1*RSW + c0) = s0;
                    *(float2*)(res_s + p2*RSW + c0) = s1;
                } else {
                    float2 r0 = *(const float2*)(h0_s + p1*RSW + c0);
                    float2 r1 = *(const float2*)(h0_s + p2*RSW + c0);
                    v0 += b0 + r0.x; v1 += b1 + r0.y;
                    v2 += b0 + r1.x; v3 += b1 + r1.y;
                }
                __half2 h0v = __floats2half2_rn(v0, v1);
                __half2 h1v = __floats2half2_rn(v2, v3);
                *(__half2*)(outb + ((size_t)(y*W + p1))*64 + c0) = h0v;
                *(__half2*)(outb + ((size_t)(y*W + p2))*64 + c0) = h1v;
                const int cw = (c0 >> 1);
                strip[(uint32_t)(130 + 1 + p1)*PXW + cw] = *(const uint32_t*)&h0v;
                strip[(uint32_t)(130 + 1 + p2)*PXW + cw] = *(const uint32_t*)&h1v;
            }
        }
        __threadfence();
        __syncthreads();
        if (tid == 0) {
            atomicExch(&g_row_flag[y], l + 1);
            if (y > 0)
                while (*(volatile int*)&g_row_flag[y - 1] < l + 1) {}
            __threadfence();
        }
        if (tid == 32 && y < 127) {
            while (*(volatile int*)&g_row_flag[y + 1] < l + 1) {}
            __threadfence();
        }
        __syncthreads();

        for (int i = tid; i < 2080; i += 256) {
            int rr = i / 1040, rem = i - rr*1040;
            int j = rem >> 3, c = rem & 7;
            int r = rr*2;
            int gy = y - 1 + r, gx = j - 1;
            if (gy >= 0 && gy < H && gx >= 0 && gx < W)
                cp_async16_cg(smaddr + (uint32_t)((r*130 + j)*PXW + c*4)*4,
                              outb + ((size_t)(gy*W + gx))*64 + c*8);
        }
        cp_commit();
        cp_wait<0>();
        __syncthreads();
    }

    for (int grp = 0; grp < 4; grp++) {
        float acc[2][4][4];
#pragma unroll
        for (int a = 0; a < 2; a++)
#pragma unroll
            for (int b = 0; b < 4; b++)
#pragma unroll
                for (int c = 0; c < 4; c++) acc[a][b][c] = 0.f;

        for (int tap = 0; tap < 9; tap++) {
            const int dy = tap/3, dx = tap%3;
            const uint32_t* wb = wsm + tap*(64*PXW);
            const uint32_t* arow0 = strip + (uint32_t)(dy*130 + dx)*PXW;
#pragma unroll
            for (int ks = 0; ks < 4; ks++) {
                const int kw = ks*8 + t;
                uint32_t af[2][4];
#pragma unroll
                for (int mt = 0; mt < 2; mt++) {
                    const uint32_t* ar = arow0 + (uint32_t)(m0 + mt*16 + g)*PXW + kw;
                    af[mt][0] = ar[0];
                    af[mt][1] = ar[8*PXW];
                    af[mt][2] = ar[4];
                    af[mt][3] = ar[8*PXW + 4];
                }
#pragma unroll
                for (int nt = 0; nt < 4; nt++) {
                    const uint32_t* bw = wb + (uint32_t)(n0 + nt*8 + g)*PXW + kw;
                    uint32_t b0 = bw[0], b1 = bw[4];
                    mma16(acc[0][nt], af[0][0], af[0][1], af[0][2], af[0][3], b0, b1);
                    mma16(acc[1][nt], af[1][0], af[1][1], af[1][2], af[1][3], b0, b1);
                }
            }
        }
        __syncthreads();

        if (grp < 3) {
            const __half* wnext = wl0 + (size_t)(grp + 1)*36864;
            for (int i = tid; i < 4608; i += 256) {
                int n2 = i >> 3, j = i & 7;
                cp_async16(wbase + (uint32_t)(n2*PXW + j*4)*4, wnext + n2*64 + j*8);
            }
            cp_commit();
        }

#pragma unroll
        for (int mt = 0; mt < 2; mt++) {
            const int p1 = m0 + mt*16 + g;
            const int p2 = p1 + 8;
#pragma unroll
            for (int nt = 0; nt < 4; nt++) {
                const int c0 = n0 + nt*8 + 2*t;
                const int cc = grp*64 + c0;
                __half2 h0v = __floats2half2_rn(acc[mt][nt][0], acc[mt][nt][1]);
                __half2 h1v = __floats2half2_rn(acc[mt][nt][2], acc[mt][nt][3]);
                *(__half2*)(G + ((size_t)(y*W + p1))*256 + cc) = h0v;
                *(__half2*)(G + ((size_t)(y*W + p2))*256 + cc) = h1v;
            }
        }
        if (grp < 3) {
            cp_wait<0>();
            __syncthreads();
        }
    }
}

// ------------------------------ LIIF query + mma.sync fp16 MLP --------------
// 256 threads / 8 warps, SB=64 samples: 2 M-groups x 4 N-groups (warp M32xN64)
// __launch_bounds__(256,2) -> 2 CTAs/SM, 4 warps/SMSP.
#define QB 16
#define SB 64
#define QTHREADS 256
#define ASH 264
#define WSH 72
#define OFF_ACT 0
#define OFF_WB0 33792
#define OFF_WB1 70656
#define OFF_BIAS 107520
#define DYN_BYTES 108544

__device__ __forceinline__ void load_wchunk(uint32_t dst_base,
                                            const __half* __restrict__ Wg,
                                            int c, int tid)
{
#pragma unroll
    for (int ii = 0; ii < 8; ii++) {
        int i = tid + ii*QTHREADS;
        int n = i >> 3, j = i & 7;
        cp_async16(dst_base + (uint32_t)(n*(WSH*2) + j*16),
                   Wg + (size_t)n*256 + c*64 + j*8);
    }
}

__global__ __launch_bounds__(QTHREADS, 2)
void query_kernel(const __half* __restrict__ G,
                  const float* __restrict__ mw0,
                  const float* __restrict__ b0eff,
                  const __half* __restrict__ w1h, const float* __restrict__ b1,
                  const __half* __restrict__ w2h, const float* __restrict__ b2,
                  const __half* __restrict__ w3h, const float* __restrict__ b3,
                  const float* __restrict__ w4, const float* __restrict__ b4,
                  float* __restrict__ out)
{
    extern __shared__ char dyn[];
    uint32_t* actu = (uint32_t*)(dyn + OFF_ACT);
    __half*   acth = (__half*)(dyn + OFF_ACT);
    float*    bias_s = (float*)(dyn + OFF_BIAS);
    __shared__ int   p_s[SB];
    __shared__ float relh_s[SB], relw_s[SB], area_s[SB];
    __shared__ float pred_s[SB][4];

    const int tid  = threadIdx.x;
    const int wid  = tid >> 5;
    const int lane = tid & 31;
    const int g    = lane >> 2;
    const int t    = lane & 3;
    const int mi   = lane >> 3;      // ldmatrix matrix index
    const int rr   = lane & 7;       // ldmatrix row within matrix

    const uint32_t dynaddr = smem_u32(dyn);
    const uint32_t wbaddr[2] = {dynaddr + OFF_WB0, dynaddr + OFF_WB1};

    if (tid < SB) {
        int m  = tid;
        int q  = blockIdx.x*QB + (m >> 2);
        int oh = q >> 9, ow = q & 511;
        int r  = (m >> 1) & 1, c = m & 1;
        float sh = (oh + 0.5f)*(2.0f/512.0f) - 1.0f;
        float sw = (ow + 0.5f)*(2.0f/512.0f) - 1.0f;
        const float d = 1.0f/128.0f, EPS = 1e-6f;
        float gh = fminf(fmaxf(sh + (2.f*r - 1.f)*d, -1.f + EPS), 1.f - EPS);
        float gw = fminf(fmaxf(sw + (2.f*c - 1.f)*d, -1.f + EPS), 1.f - EPS);
        float fy = ((gh + 1.0f)*128.0f - 1.0f)*0.5f;
        float fx = ((gw + 1.0f)*128.0f - 1.0f)*0.5f;
        int iy = min(max((int)rintf(fy), 0), 127);
        int ix = min(max((int)rintf(fx), 0), 127);
        float qgh = (iy + 0.5f)*(2.0f/128.0f) - 1.0f;
        float qgw = (ix + 0.5f)*(2.0f/128.0f) - 1.0f;
        float rh = (sh - qgh)*128.0f;
        float rw = (sw - qgw)*128.0f;
        p_s[m] = iy*128 + ix;
        relh_s[m] = rh; relw_s[m] = rw;
        area_s[m] = fabsf(rh*rw);
    }

    load_wchunk(wbaddr[0], w1h, 0, tid);
    cp_commit();
    __syncthreads();

    // ---- stage 1: A0 = relu(G[p] + rel_h*U + rel_w*V + b0eff) -> fp16
    {
        const int ocw = tid & 127;
        const int oc0 = ocw*2;
        float u0 = mw0[576*256 + oc0],     u1 = mw0[576*256 + oc0 + 1];
        float v0 = mw0[577*256 + oc0],     v1 = mw0[577*256 + oc0 + 1];
        float b0v = b0eff[oc0],            b1v = b0eff[oc0 + 1];
        const __half2* G2 = (const __half2*)G;
        for (int m = (tid >> 7); m < SB; m += 2) {
            __half2 gg = G2[(size_t)p_s[m]*128 + ocw];
            float rh = relh_s[m], rw = relw_s[m];
            float x0v = fmaf(rh, u0, fmaf(rw, v0, __low2float(gg)  + b0v));
            float x1v = fmaf(rh, u1, fmaf(rw, v1, __high2float(gg) + b1v));
            __half2 hv = __floats2half2_rn(fmaxf(x0v, 0.f), fmaxf(x1v, 0.f));
            actu[m*(ASH/2) + ocw] = *(const uint32_t*)&hv;
        }
    }
    __syncthreads();

    const int m0  = (wid & 1)*32;     // 2 M-groups over 64 samples
    const int n0b = (wid >> 1)*64;    // 4 N-groups over 256 neurons

    // ---- ldmatrix lane addresses (bytes)
    uint32_t aAddr[2];
#pragma unroll
    for (int mt = 0; mt < 2; mt++) {
        int row = m0 + mt*16 + (mi & 1)*8 + rr;
        aAddr[mt] = dynaddr + OFF_ACT
                  + (uint32_t)(row*(ASH/2) + (mi >> 1)*4)*4u;
    }
    uint32_t bOff[4];
#pragma unroll
    for (int p = 0; p < 4; p++) {
        int row = n0b + (2*p + (mi >> 1))*8 + rr;
        bOff[p] = (uint32_t)(row*(WSH/2) + (mi & 1)*4)*4u;
    }

    const __half* Ws[3] = {w1h, w2h, w3h};
    const float*  Bs[3] = {b1, b2, b3};

    int cnt = 0;
    for (int L = 0; L < 3; L++) {
        bias_s[tid] = Bs[L][tid];

        float acc[2][8][4];
#pragma unroll
        for (int mt = 0; mt < 2; mt++)
#pragma unroll
            for (int nt = 0; nt < 8; nt++)
#pragma unroll
                for (int i = 0; i < 4; i++) acc[mt][nt][i] = 0.f;

        for (int c = 0; c < 4; c++) {
            const bool has_next = (c < 3) || (L < 2);
            if (has_next) {
                const __half* Wn = (c < 3) ? Ws[L] : Ws[L+1];
                const int cn = (c < 3) ? c + 1 : 0;
                load_wchunk(wbaddr[(cnt + 1) & 1], Wn, cn, tid);
                cp_commit();
                cp_wait<1>();
            } else {
                cp_wait<0>();
            }
            __syncthreads();

            const uint32_t wbA = wbaddr[cnt & 1];
#pragma unroll
            for (int ks = 0; ks < 4; ks++) {
                const uint32_t kbyte = (uint32_t)(c*32 + ks*8)*4u;
                uint32_t af[2][4];
                ldsm4(af[0][0], af[0][1], af[0][2], af[0][3], aAddr[0] + kbyte);
                ldsm4(af[1][0], af[1][1], af[1][2], af[1][3], aAddr[1] + kbyte);
                const uint32_t kb = (uint32_t)(ks*8)*4u;
#pragma unroll
                for (int p = 0; p < 4; p++) {
                    uint32_t b0a, b1a, b0b, b1b;
                    ldsm4(b0a, b1a, b0b, b1b, wbA + bOff[p] + kb);
                    mma16(acc[0][2*p],   af[0][0], af[0][1], af[0][2], af[0][3], b0a, b1a);
                    mma16(acc[1][2*p],   af[1][0], af[1][1], af[1][2], af[1][3], b0a, b1a);
                    mma16(acc[0][2*p+1], af[0][0], af[0][1], af[0][2], af[0][3], b0b, b1b);
                    mma16(acc[1][2*p+1], af[1][0], af[1][1], af[1][2], af[1][3], b0b, b1b);
                }
            }
            cnt++;
            __syncthreads();
        }

#pragma unroll
        for (int mt = 0; mt < 2; mt++) {
            const int r0 = m0 + mt*16 + g;
#pragma unroll
            for (int nt = 0; nt < 8; nt++) {
                const int col = n0b + nt*8 + 2*t;
                float v0 = fmaxf(acc[mt][nt][0] + bias_s[col],     0.f);
                float v1 = fmaxf(acc[mt][nt][1] + bias_s[col + 1], 0.f);
                float v2 = fmaxf(acc[mt][nt][2] + bias_s[col],     0.f);
                float v3 = fmaxf(acc[mt][nt][3] + bias_s[col + 1], 0.f);
                __half2 h01 = __floats2half2_rn(v0, v1);
                __half2 h23 = __floats2half2_rn(v2, v3);
                const int cw = (n0b >> 1) + nt*4 + t;
                actu[r0*(ASH/2) + cw]     = *(const uint32_t*)&h01;
                actu[(r0+8)*(ASH/2) + cw] = *(const uint32_t*)&h23;
            }
        }
        __syncthreads();
    }

    // ---- stage 3: output layer 256->3 (fp32 accumulate over fp16 acts)
    {
        float* wsm = (float*)(dyn + OFF_WB0);
        for (int i = tid; i < 768; i += QTHREADS) wsm[i] = w4[i];
        __syncthreads();
        if (tid < SB) {
            const __half* ap = acth + tid*ASH;
            float s0 = b4[0], s1 = b4[1], s2 = b4[2];
#pragma unroll 4
            for (int k = 0; k < 256; k++) {
                float a = __half2float(ap[k]);
                s0 = fmaf(a, wsm[k*3 + 0], s0);
                s1 = fmaf(a, wsm[k*3 + 1], s1);
                s2 = fmaf(a, wsm[k*3 + 2], s2);
            }
            pred_s[tid][0] = s0; pred_s[tid][1] = s1; pred_s[tid][2] = s2;
        }
    }
    __syncthreads();

    if (tid < QB) {
        int bb = tid*4;
        float a0 = area_s[bb+0], a1 = area_s[bb+1];
        float a2 = area_s[bb+2], a3 = area_s[bb+3];
        float tot = a0 + a1 + a2 + a3 + 1e-9f;
        int q = blockIdx.x*QB + tid;
#pragma unroll
        for (int j = 0; j < 3; j++) {
            float num = pred_s[bb+0][j]*a3 + pred_s[bb+1][j]*a2
                      + pred_s[bb+2][j]*a1 + pred_s[bb+3][j]*a0;
            float yv = num / tot;
            yv = fminf(fmaxf(yv, 0.f), 1.f);
            out[(size_t)j*NQ + q] = yv;
        }
    }
}

// ------------------------------ launch --------------------------------------
extern "C" void kernel_launch(void* const* d_in, const int* in_sizes, int n_in,
                              void* d_out, int out_size)
{
    const float* x      = (const float*)d_in[0];
    const float* head_w = (const float*)d_in[2];
    const float* head_b = (const float*)d_in[3];
    const float* rb_w   = (const float*)d_in[4];
    const float* rb_b   = (const float*)d_in[5];
    const float* tail_w = (const float*)d_in[6];
    const float* tail_b = (const float*)d_in[7];
    const float* mw0 = (const float*)d_in[8];
    const float* mb0 = (const float*)d_in[9];
    const float* mw1 = (const float*)d_in[10];
    const float* mb1 = (const float*)d_in[11];
    const float* mw2 = (const float*)d_in[12];
    const float* mb2 = (const float*)d_in[13];
    const float* mw3 = (const float*)d_in[14];
    const float* mb3 = (const float*)d_in[15];
    const float* mw4 = (const float*)d_in[16];
    const float* mb4 = (const float*)d_in[17];
    float* out = (float*)d_out;

    float *h0, *b0eff;
    __half *h0h, *Ah, *Bh, *G, *w1h, *w2h, *w3h, *wch, *wl0;
    cudaGetSymbolAddress((void**)&h0, g_h0);
    cudaGetSymbolAddress((void**)&h0h, g_h0h);
    cudaGetSymbolAddress((void**)&Ah,  g_Ah);
    cudaGetSymbolAddress((void**)&Bh,  g_Bh);
    cudaGetSymbolAddress((void**)&G,  g_G);
    cudaGetSymbolAddress((void**)&b0eff, g_b0eff);
    cudaGetSymbolAddress((void**)&w1h, g_w1h);
    cudaGetSymbolAddress((void**)&w2h, g_w2h);
    cudaGetSymbolAddress((void**)&w3h, g_w3h);
    cudaGetSymbolAddress((void**)&wch, g_wch);
    cudaGetSymbolAddress((void**)&wl0, g_wl0);

    prep_all<<<(PREP_TOTAL + 255)/256, 256>>>(rb_w, tail_w, mw0, mb0,
                                              mw1, mw2, mw3,
                                              wch, wl0, w1h, w2h, w3h, b0eff);

    conv_head<<<dim3(W/CTX, H/CTY, 4), dim3(CTX, CTY)>>>(x, head_w, head_b,
                                                         h0, h0h);

    cudaFuncSetAttribute(fused_conv,
                         cudaFuncAttributeMaxDynamicSharedMemorySize, FSMEM);
    fused_conv<<<128, 256, FSMEM>>>(h0h, h0, wch, rb_b, tail_b, wl0,
                                    Ah, Bh, G);

    cudaFuncSetAttribute(query_kernel,
                         cudaFuncAttributeMaxDynamicSharedMemorySize,
                         DYN_BYTES);
    query_kernel<<<NQ/QB, QTHREADS, DYN_BYTES>>>(
        G, mw0, b0eff, w1h, mb1, w2h, mb2, w3h, mb3, mw4, mb4, out);
}

// round 15
// speedup vs baseline: 1.3371x; 1.2379x over previous
#include <cuda_runtime.h>
#include <cuda_fp16.h>
#include <cstdint>

#define H 128
#define W 128
#define HW 16384
#define OH 512
#define OWID 512
#define NQ (OH*OWID)

// ------------------------------ scratch (device globals, no allocation) ----
__device__ __align__(16) float g_h0[64*HW];      // fp32 NHWC (head conv out)
__device__ __align__(16) __half g_h0h[64*HW];    // fp16 NHWC
__device__ __align__(16) __half g_Ah [64*HW];    // ping-pong fp16 buffers
__device__ __align__(16) __half g_Bh [64*HW];
__device__ __align__(16) __half g_G [(size_t)HW*256];
__device__ float g_b0eff[256];
__device__ __align__(16) __half g_w1h[65536];    // fragment-packed MLP weights
__device__ __align__(16) __half g_w2h[65536];
__device__ __align__(16) __half g_w3h[65536];
__device__ __align__(16) __half g_wch[33*36864]; // fp16 conv weights [cv][tap][n][ic]
__device__ __align__(16) __half g_wl0[4*36864];  // fp16 layer-0 conv weights
__device__ unsigned g_bar_cnt;
__device__ volatile unsigned g_bar_gen;
__device__ int g_row_flag[128];

// ------------------------------ PTX helpers --------------------------------
__device__ __forceinline__ uint32_t smem_u32(const void* p) {
    uint32_t a;
    asm("{ .reg .u64 t; cvta.to.shared.u64 t, %1; cvt.u32.u64 %0, t; }"
        : "=r"(a) : "l"(p));
    return a;
}
__device__ __forceinline__ void cp_async16(uint32_t dst, const void* src) {
    asm volatile("cp.async.ca.shared.global [%0], [%1], 16;"
                 :: "r"(dst), "l"(src) : "memory");
}
__device__ __forceinline__ void cp_async16_cg(uint32_t dst, const void* src) {
    asm volatile("cp.async.cg.shared.global [%0], [%1], 16;"
                 :: "r"(dst), "l"(src) : "memory");
}
__device__ __forceinline__ void cp_commit() {
    asm volatile("cp.async.commit_group;" ::: "memory");
}
template<int N> __device__ __forceinline__ void cp_wait() {
    asm volatile("cp.async.wait_group %0;" :: "n"(N) : "memory");
}
// m16n8k16 f16 MMA, A row-major, B col-major, f32 accumulate (in-place)
__device__ __forceinline__ void mma16(float* d,
                                      uint32_t a0, uint32_t a1, uint32_t a2, uint32_t a3,
                                      uint32_t b0, uint32_t b1) {
    asm volatile(
        "mma.sync.aligned.m16n8k16.row.col.f32.f16.f16.f32 "
        "{%0,%1,%2,%3},{%4,%5,%6,%7},{%8,%9},{%0,%1,%2,%3};"
        : "+f"(d[0]), "+f"(d[1]), "+f"(d[2]), "+f"(d[3])
        : "r"(a0), "r"(a1), "r"(a2), "r"(a3), "r"(b0), "r"(b1));
}
// ldmatrix x4 (b16, non-transposed)
__device__ __forceinline__ void ldsm4(uint32_t& r0, uint32_t& r1,
                                      uint32_t& r2, uint32_t& r3, uint32_t addr) {
    asm volatile("ldmatrix.sync.aligned.m8n8.x4.shared.b16 {%0,%1,%2,%3}, [%4];"
                 : "=r"(r0), "=r"(r1), "=r"(r2), "=r"(r3) : "r"(addr));
}

// software grid barrier (all 128 CTAs resident; generation-based = replay-safe)
__device__ __forceinline__ void grid_barrier() {
    __syncthreads();
    if (threadIdx.x == 0) {
        __threadfence();
        unsigned gen = g_bar_gen;
        if (atomicAdd(&g_bar_cnt, 1u) == 127u) {
            atomicExch(&g_bar_cnt, 0u);
            __threadfence();
            g_bar_gen = gen + 1u;
        } else {
            while (g_bar_gen == gen) {}
        }
        __threadfence();
    }
    __syncthreads();
}

// ------------------------------ head conv (IC=3), NCHW in -> NHWC out -------
#define CTX 32
#define CTY 4
__global__ void conv_head(const float* __restrict__ x,
                          const float* __restrict__ w,
                          const float* __restrict__ bias,
                          float* __restrict__ out,
                          __half* __restrict__ outh)
{
    __shared__ float in_s[3][CTY+2][CTX+2];
    __shared__ float w_s[3*9*16];
    const int tx = threadIdx.x, ty = threadIdx.y;
    const int tid = ty*CTX + tx;
    const int x0 = blockIdx.x*CTX, y0 = blockIdx.y*CTY;
    const int ocg0 = blockIdx.z*16;

    float acc[16];
#pragma unroll
    for (int i = 0; i < 16; i++) acc[i] = 0.f;

    const int tot = 3*(CTY+2)*(CTX+2);
    for (int i = tid; i < tot; i += CTX*CTY) {
        int ic  = i / ((CTY+2)*(CTX+2));
        int rem = i % ((CTY+2)*(CTX+2));
        int ly = rem / (CTX+2), lx = rem % (CTX+2);
        int gy = y0 - 1 + ly, gx = x0 - 1 + lx;
        float v = 0.f;
        if (gy >= 0 && gy < H && gx >= 0 && gx < W)
            v = x[(size_t)ic*HW + gy*W + gx];
        in_s[ic][ly][lx] = v;
    }
    for (int i = tid; i < 3*9*16; i += CTX*CTY) {
        int oc = i & 15;
        int t2 = i >> 4;
        int tap = t2 % 9, ic = t2 / 9;
        w_s[(ic*9+tap)*16 + oc] = w[(size_t)(ocg0+oc)*27 + ic*9 + tap];
    }
    __syncthreads();
    for (int ic = 0; ic < 3; ic++) {
#pragma unroll
        for (int tap = 0; tap < 9; tap++) {
            const int dy = tap/3, dx = tap%3;
            float a = in_s[ic][ty+dy][tx+dx];
            const float4* wp = (const float4*)&w_s[(ic*9+tap)*16];
            float wv[16];
            *(float4*)&wv[0]  = wp[0];
            *(float4*)&wv[4]  = wp[1];
            *(float4*)&wv[8]  = wp[2];
            *(float4*)&wv[12] = wp[3];
#pragma unroll
            for (int oc = 0; oc < 16; oc++)
                acc[oc] = fmaf(a, wv[oc], acc[oc]);
        }
    }
    const int pix = (y0+ty)*W + (x0+tx);
    float4* o4 = (float4*)(out + (size_t)pix*64 + ocg0);
    __half2* oh2 = (__half2*)(outh + (size_t)pix*64 + ocg0);
#pragma unroll
    for (int v = 0; v < 4; v++) {
        float4 r;
        r.x = acc[v*4+0] + bias[ocg0+v*4+0];
        r.y = acc[v*4+1] + bias[ocg0+v*4+1];
        r.z = acc[v*4+2] + bias[ocg0+v*4+2];
        r.w = acc[v*4+3] + bias[ocg0+v*4+3];
        o4[v] = r;
        oh2[v*2]   = __floats2half2_rn(r.x, r.y);
        oh2[v*2+1] = __floats2half2_rn(r.z, r.w);
    }
}

// ------------------------------ merged weight transforms --------------------
#define N_WCH (33*36864)
#define N_WL0 (4*36864)
#define N_W123 (3*65536)
#define PREP_TOTAL (N_WCH + N_WL0 + N_W123 + 256)

__global__ void prep_all(const float* __restrict__ rb_w,
                         const float* __restrict__ tail_w,
                         const float* __restrict__ mw0,
                         const float* __restrict__ mb0,
                         const float* __restrict__ mw1,
                         const float* __restrict__ mw2,
                         const float* __restrict__ mw3,
                         __half* __restrict__ wch,
                         __half* __restrict__ wl0,
                         __half* __restrict__ wh1,
                         __half* __restrict__ wh2,
                         __half* __restrict__ wh3,
                         float* __restrict__ b0eff)
{
    int i = blockIdx.x*256 + threadIdx.x;
    if (i < N_WCH) {
        int cv = i / 36864;
        int r  = i % 36864;
        int tap = r >> 12;
        int r2  = r & 4095;
        int n   = r2 >> 6;
        int ic  = r2 & 63;
        const float* src = (cv < 32) ? (rb_w + (size_t)cv*36864) : tail_w;
        wch[i] = __float2half(src[(size_t)n*576 + ic*9 + tap]);
        return;
    }
    i -= N_WCH;
    if (i < N_WL0) {
        int grp = i / 36864;
        int r  = i % 36864;
        int tap = r >> 12;
        int r2  = r & 4095;
        int n   = r2 >> 6;
        int ic  = r2 & 63;
        int ng = grp*64 + n;
        wl0[i] = __float2half(mw0[(size_t)(ic*9 + tap)*256 + ng]);
        return;
    }
    i -= N_WL0;
    if (i < N_W123) {
        // fragment-packed B layout: entry = ((c*32 + j)*4 + ks)*32 + lane,
        // 4 halfs per entry: B[row][k0], B[row][k0+1], B[row][k0+8], B[row][k0+9]
        // row = j*8 + (lane>>2), k0 = c*64 + ks*16 + 2*(lane&3); B[n][k] = w[k*256+n]
        int which = i >> 16;
        int idx = i & 65535;
        int hh    = idx & 3;
        int entry = idx >> 2;
        int lane = entry & 31;
        int ks   = (entry >> 5) & 3;
        int j    = (entry >> 7) & 31;
        int c    = entry >> 12;
        int gg = lane >> 2, tt = lane & 3;
        int row = j*8 + gg;
        int k = c*64 + ks*16 + 2*tt + (hh & 1) + (hh >> 1)*8;
        const float* w = (which == 0) ? mw1 : (which == 1) ? mw2 : mw3;
        __half* wh = (which == 0) ? wh1 : (which == 1) ? wh2 : wh3;
        wh[idx] = __float2half(w[k*256 + row]);
        return;
    }
    i -= N_W123;
    if (i < 256)
        b0eff[i] = mb0[i] + 0.5f*mw0[578*256 + i] + 0.5f*mw0[579*256 + i];
}

// ------------------------------ fused persistent conv chain -----------------
// 128 CTAs, one per image row, neighbor-flag synchronized.
#define PXW 36
#define STRIPW2 (3*130*PXW)              // 14040 words
#define WTW (9*64*PXW)                   // 20736 words
#define RSW 68
#define OFF_RES (STRIPW2 + WTW)
#define OFF_H0  (OFF_RES + 128*RSW)
#define FSM_WORDS (OFF_H0 + 128*RSW)
#define FSMEM (FSM_WORDS*4)              // 208736 bytes

__global__ void __launch_bounds__(256) fused_conv(
    const __half* __restrict__ h0h, const float* __restrict__ h0f,
    const __half* __restrict__ wch, const float* __restrict__ rb_b,
    const float* __restrict__ tail_b, const __half* __restrict__ wl0,
    __half* __restrict__ bufA, __half* __restrict__ bufB,
    __half* __restrict__ G)
{
    extern __shared__ uint32_t sm[];
    uint32_t* strip = sm;
    uint32_t* wsm   = sm + STRIPW2;
    float* res_s = (float*)(sm + OFF_RES);
    float* h0_s  = (float*)(sm + OFF_H0);
    __shared__ float bias_s[64];

    const int tid = threadIdx.x, wid = tid >> 5, lane = tid & 31;
    const int g = lane >> 2, t = lane & 3;
    const int y = blockIdx.x;
    const uint32_t smaddr  = smem_u32(sm);
    const uint32_t wbase   = smaddr + STRIPW2*4;
    const uint32_t resaddr = smaddr + OFF_RES*4;
    const uint32_t h0addr  = smaddr + OFF_H0*4;

    {
        uint4 z = {0, 0, 0, 0};
        uint4* s4 = (uint4*)sm;
        for (int i = tid; i < STRIPW2/4; i += 256) s4[i] = z;
    }
    __syncthreads();

    for (int i = tid; i < 3120; i += 256) {
        int r = i / 1040, rem = i - r*1040;
        int j = rem >> 3, c = rem & 7;
        int gy = y - 1 + r, gx = j - 1;
        if (gy >= 0 && gy < H && gx >= 0 && gx < W)
            cp_async16(smaddr + (uint32_t)((r*130 + j)*PXW + c*4)*4,
                       h0h + ((size_t)(gy*W + gx))*64 + c*8);
    }
    for (int i = tid; i < 2048; i += 256) {
        int px = i >> 4, c = i & 15;
        const float* src = h0f + ((size_t)(y*W + px))*64 + c*4;
        cp_async16(resaddr + (uint32_t)(px*RSW + c*4)*4, src);
        cp_async16(h0addr  + (uint32_t)(px*RSW + c*4)*4, src);
    }
    for (int i = tid; i < 4608; i += 256) {
        int n2 = i >> 3, j = i & 7;
        cp_async16(wbase + (uint32_t)(n2*PXW + j*4)*4, wch + n2*64 + j*8);
    }
    cp_commit();

    if (tid == 0) g_row_flag[y] = 0;
    grid_barrier();

    cp_wait<0>();
    __syncthreads();

    const int m0 = (wid & 3)*32, n0 = (wid >> 2)*32;
    __half* bufs[2] = {bufA, bufB};

    for (int l = 0; l < 33; l++) {
        if (tid < 64) bias_s[tid] = (l < 32) ? rb_b[l*64 + tid] : tail_b[tid];

        float acc[2][4][4];
#pragma unroll
        for (int a = 0; a < 2; a++)
#pragma unroll
            for (int b = 0; b < 4; b++)
#pragma unroll
                for (int c = 0; c < 4; c++) acc[a][b][c] = 0.f;

        for (int tap = 0; tap < 9; tap++) {
            const int dy = tap/3, dx = tap%3;
            const uint32_t* wb = wsm + tap*(64*PXW);
            const uint32_t* arow0 = strip + (uint32_t)(dy*130 + dx)*PXW;
#pragma unroll
            for (int ks = 0; ks < 4; ks++) {
                const int kw = ks*8 + t;
                uint32_t af[2][4];
#pragma unroll
                for (int mt = 0; mt < 2; mt++) {
                    const uint32_t* ar = arow0 + (uint32_t)(m0 + mt*16 + g)*PXW + kw;
                    af[mt][0] = ar[0];
                    af[mt][1] = ar[8*PXW];
                    af[mt][2] = ar[4];
                    af[mt][3] = ar[8*PXW + 4];
                }
#pragma unroll
                for (int nt = 0; nt < 4; nt++) {
                    const uint32_t* bw = wb + (uint32_t)(n0 + nt*8 + g)*PXW + kw;
                    uint32_t b0 = bw[0], b1 = bw[4];
                    mma16(acc[0][nt], af[0][0], af[0][1], af[0][2], af[0][3], b0, b1);
                    mma16(acc[1][nt], af[1][0], af[1][1], af[1][2], af[1][3], b0, b1);
                }
            }
        }
        __syncthreads();

        const __half* wnext = (l < 32) ? (wch + (size_t)(l + 1)*36864) : wl0;
        for (int i = tid; i < 4608; i += 256) {
            int n2 = i >> 3, j = i & 7;
            cp_async16(wbase + (uint32_t)(n2*PXW + j*4)*4, wnext + n2*64 + j*8);
        }
        cp_commit();

        __half* outb = bufs[l & 1];
        const int mode = (l == 32) ? 2 : (l & 1);
#pragma unroll
        for (int mt = 0; mt < 2; mt++) {
            const int p1 = m0 + mt*16 + g;
            const int p2 = p1 + 8;
#pragma unroll
            for (int nt = 0; nt < 4; nt++) {
                const int c0 = n0 + nt*8 + 2*t;
                float v0 = acc[mt][nt][0], v1 = acc[mt][nt][1];
                float v2 = acc[mt][nt][2], v3 = acc[mt][nt][3];
                float b0 = bias_s[c0], b1 = bias_s[c0 + 1];
                if (mode == 0) {
                    v0 = fmaxf(v0 + b0, 0.f); v1 = fmaxf(v1 + b1, 0.f);
                    v2 = fmaxf(v2 + b0, 0.f); v3 = fmaxf(v3 + b1, 0.f);
                } else if (mode == 1) {
                    float2 r0 = *(const float2*)(res_s + p1*RSW + c0);
                    float2 r1 = *(const float2*)(res_s + p2*RSW + c0);
                    v0 += b0 + r0.x; v1 += b1 + r0.y;
                    v2 += b0 + r1.x; v3 += b1 + r1.y;
                    float2 s0 = {v0, v1}, s1 = {v2, v3};
                    *(float2*)(res_s + p1*RSW + c0) = s0;
                    *(float2*)(res_s + p2*RSW + c0) = s1;
                } else {
                    float2 r0 = *(const float2*)(h0_s + p1*RSW + c0);
                    float2 r1 = *(const float2*)(h0_s + p2*RSW + c0);
                    v0 += b0 + r0.x; v1 += b1 + r0.y;
                    v2 += b0 + r1.x; v3 += b1 + r1.y;
                }
                __half2 h0v = __floats2half2_rn(v0, v1);
                __half2 h1v = __floats2half2_rn(v2, v3);
                *(__half2*)(outb + ((size_t)(y*W + p1))*64 + c0) = h0v;
                *(__half2*)(outb + ((size_t)(y*W + p2))*64 + c0) = h1v;
                const int cw = (c0 >> 1);
                strip[(uint32_t)(130 + 1 + p1)*PXW + cw] = *(const uint32_t*)&h0v;
                strip[(uint32_t)(130 + 1 + p2)*PXW + cw] = *(const uint32_t*)&h1v;
            }
        }
        __threadfence();
        __syncthreads();
        if (tid == 0) {
            atomicExch(&g_row_flag[y], l + 1);
            if (y > 0)
                while (*(volatile int*)&g_row_flag[y - 1] < l + 1) {}
            __threadfence();
        }
        if (tid == 32 && y < 127) {
            while (*(volatile int*)&g_row_flag[y + 1] < l + 1) {}
            __threadfence();
        }
        __syncthreads();

        for (int i = tid; i < 2080; i += 256) {
            int rr = i / 1040, rem = i - rr*1040;
            int j = rem >> 3, c = rem & 7;
            int r = rr*2;
            int gy = y - 1 + r, gx = j - 1;
            if (gy >= 0 && gy < H && gx >= 0 && gx < W)
                cp_async16_cg(smaddr + (uint32_t)((r*130 + j)*PXW + c*4)*4,
                              outb + ((size_t)(gy*W + gx))*64 + c*8);
        }
        cp_commit();
        cp_wait<0>();
        __syncthreads();
    }

    for (int grp = 0; grp < 4; grp++) {
        float acc[2][4][4];
#pragma unroll
        for (int a = 0; a < 2; a++)
#pragma unroll
            for (int b = 0; b < 4; b++)
#pragma unroll
                for (int c = 0; c < 4; c++) acc[a][b][c] = 0.f;

        for (int tap = 0; tap < 9; tap++) {
            const int dy = tap/3, dx = tap%3;
            const uint32_t* wb = wsm + tap*(64*PXW);
            const uint32_t* arow0 = strip + (uint32_t)(dy*130 + dx)*PXW;
#pragma unroll
            for (int ks = 0; ks < 4; ks++) {
                const int kw = ks*8 + t;
                uint32_t af[2][4];
#pragma unroll
                for (int mt = 0; mt < 2; mt++) {
                    const uint32_t* ar = arow0 + (uint32_t)(m0 + mt*16 + g)*PXW + kw;
                    af[mt][0] = ar[0];
                    af[mt][1] = ar[8*PXW];
                    af[mt][2] = ar[4];
                    af[mt][3] = ar[8*PXW + 4];
                }
#pragma unroll
                for (int nt = 0; nt < 4; nt++) {
                    const uint32_t* bw = wb + (uint32_t)(n0 + nt*8 + g)*PXW + kw;
                    uint32_t b0 = bw[0], b1 = bw[4];
                    mma16(acc[0][nt], af[0][0], af[0][1], af[0][2], af[0][3], b0, b1);
                    mma16(acc[1][nt], af[1][0], af[1][1], af[1][2], af[1][3], b0, b1);
                }
            }
        }
        __syncthreads();

        if (grp < 3) {
            const __half* wnext = wl0 + (size_t)(grp + 1)*36864;
            for (int i = tid; i < 4608; i += 256) {
                int n2 = i >> 3, j = i & 7;
                cp_async16(wbase + (uint32_t)(n2*PXW + j*4)*4, wnext + n2*64 + j*8);
            }
            cp_commit();
        }

#pragma unroll
        for (int mt = 0; mt < 2; mt++) {
            const int p1 = m0 + mt*16 + g;
            const int p2 = p1 + 8;
#pragma unroll
            for (int nt = 0; nt < 4; nt++) {
                const int c0 = n0 + nt*8 + 2*t;
                const int cc = grp*64 + c0;
                __half2 h0v = __floats2half2_rn(acc[mt][nt][0], acc[mt][nt][1]);
                __half2 h1v = __floats2half2_rn(acc[mt][nt][2], acc[mt][nt][3]);
                *(__half2*)(G + ((size_t)(y*W + p1))*256 + cc) = h0v;
                *(__half2*)(G + ((size_t)(y*W + p2))*256 + cc) = h1v;
            }
        }
        if (grp < 3) {
            cp_wait<0>();
            __syncthreads();
        }
    }
}

// ------------------------------ LIIF query + mma.sync fp16 MLP --------------
// 256 threads / 8 warps, SB=64: 2 M-groups x 4 N-groups. B operands via LDG
// from fragment-packed global layout (no smem staging for weights).
#define QB 16
#define SB 64
#define QTHREADS 256
#define ASH 264
#define OFF_ACT 0
#define OFF_BIAS 33792
#define DYN_BYTES 36864

__global__ __launch_bounds__(QTHREADS, 2)
void query_kernel(const __half* __restrict__ G,
                  const float* __restrict__ mw0,
                  const float* __restrict__ b0eff,
                  const __half* __restrict__ w1h, const float* __restrict__ b1,
                  const __half* __restrict__ w2h, const float* __restrict__ b2,
                  const __half* __restrict__ w3h, const float* __restrict__ b3,
                  const float* __restrict__ w4, const float* __restrict__ b4,
                  float* __restrict__ out)
{
    extern __shared__ char dyn[];
    uint32_t* actu = (uint32_t*)(dyn + OFF_ACT);
    __half*   acth = (__half*)(dyn + OFF_ACT);
    float*    bias3 = (float*)(dyn + OFF_BIAS);   // [3][256]
    __shared__ int   p_s[SB];
    __shared__ float relh_s[SB], relw_s[SB], area_s[SB];
    __shared__ float pred_s[SB][4];

    const int tid  = threadIdx.x;
    const int wid  = tid >> 5;
    const int lane = tid & 31;
    const int g    = lane >> 2;
    const int t    = lane & 3;
    const int mi   = lane >> 3;      // ldmatrix matrix index
    const int rr   = lane & 7;       // ldmatrix row within matrix

    const uint32_t dynaddr = smem_u32(dyn);

    if (tid < SB) {
        int m  = tid;
        int q  = blockIdx.x*QB + (m >> 2);
        int oh = q >> 9, ow = q & 511;
        int r  = (m >> 1) & 1, c = m & 1;
        float sh = (oh + 0.5f)*(2.0f/512.0f) - 1.0f;
        float sw = (ow + 0.5f)*(2.0f/512.0f) - 1.0f;
        const float d = 1.0f/128.0f, EPS = 1e-6f;
        float gh = fminf(fmaxf(sh + (2.f*r - 1.f)*d, -1.f + EPS), 1.f - EPS);
        float gw = fminf(fmaxf(sw + (2.f*c - 1.f)*d, -1.f + EPS), 1.f - EPS);
        float fy = ((gh + 1.0f)*128.0f - 1.0f)*0.5f;
        float fx = ((gw + 1.0f)*128.0f - 1.0f)*0.5f;
        int iy = min(max((int)rintf(fy), 0), 127);
        int ix = min(max((int)rintf(fx), 0), 127);
        float qgh = (iy + 0.5f)*(2.0f/128.0f) - 1.0f;
        float qgw = (ix + 0.5f)*(2.0f/128.0f) - 1.0f;
        float rh = (sh - qgh)*128.0f;
        float rw = (sw - qgw)*128.0f;
        p_s[m] = iy*128 + ix;
        relh_s[m] = rh; relw_s[m] = rw;
        area_s[m] = fabsf(rh*rw);
    }
    // preload all 3 layer biases
    bias3[tid]       = b1[tid];
    bias3[256 + tid] = b2[tid];
    bias3[512 + tid] = b3[tid];
    __syncthreads();

    // ---- stage 1: A0 = relu(G[p] + rel_h*U + rel_w*V + b0eff) -> fp16
    {
        const int ocw = tid & 127;
        const int oc0 = ocw*2;
        float u0 = mw0[576*256 + oc0],     u1 = mw0[576*256 + oc0 + 1];
        float v0 = mw0[577*256 + oc0],     v1 = mw0[577*256 + oc0 + 1];
        float b0v = b0eff[oc0],            b1v = b0eff[oc0 + 1];
        const __half2* G2 = (const __half2*)G;
        for (int m = (tid >> 7); m < SB; m += 2) {
            __half2 gg = G2[(size_t)p_s[m]*128 + ocw];
            float rh = relh_s[m], rw = relw_s[m];
            float x0v = fmaf(rh, u0, fmaf(rw, v0, __low2float(gg)  + b0v));
            float x1v = fmaf(rh, u1, fmaf(rw, v1, __high2float(gg) + b1v));
            __half2 hv = __floats2half2_rn(fmaxf(x0v, 0.f), fmaxf(x1v, 0.f));
            actu[m*(ASH/2) + ocw] = *(const uint32_t*)&hv;
        }
    }
    __syncthreads();

    const int m0  = (wid & 1)*32;     // 2 M-groups over 64 samples
    const int n0b = (wid >> 1)*64;    // 4 N-groups over 256 neurons
    const int jbase = (wid >> 1)*8;   // fragment-packed j base

    // ---- ldmatrix lane addresses for A (bytes)
    uint32_t aAddr[2];
#pragma unroll
    for (int mt = 0; mt < 2; mt++) {
        int row = m0 + mt*16 + (mi & 1)*8 + rr;
        aAddr[mt] = dynaddr + OFF_ACT
                  + (uint32_t)(row*(ASH/2) + (mi >> 1)*4)*4u;
    }

    const __half* Ws[3] = {w1h, w2h, w3h};

    for (int L = 0; L < 3; L++) {
        const uint2* Wq = (const uint2*)Ws[L];
        const float* bias_s = bias3 + L*256;

        float acc[2][8][4];
#pragma unroll
        for (int mt = 0; mt < 2; mt++)
#pragma unroll
            for (int nt = 0; nt < 8; nt++)
#pragma unroll
                for (int i = 0; i < 4; i++) acc[mt][nt][i] = 0.f;

#pragma unroll
        for (int c = 0; c < 4; c++) {
#pragma unroll
            for (int ks = 0; ks < 4; ks++) {
                const uint32_t kbyte = (uint32_t)(c*32 + ks*8)*4u;
                uint32_t af[2][4];
                ldsm4(af[0][0], af[0][1], af[0][2], af[0][3], aAddr[0] + kbyte);
                ldsm4(af[1][0], af[1][1], af[1][2], af[1][3], aAddr[1] + kbyte);
                // B fragments from global (fragment-packed): entry index =
                // ((c*32 + j)*4 + ks)*32 + lane ; j = jbase + 2p (+1)
                uint2 f[4][2];
#pragma unroll
                for (int p = 0; p < 4; p++) {
                    const uint2* q = Wq
                        + ((size_t)((c*32 + jbase + 2*p)*4 + ks)*32 + lane);
                    f[p][0] = __ldg(q);
                    f[p][1] = __ldg(q + 128);   // j+1 -> +4*32 entries
                }
#pragma unroll
                for (int p = 0; p < 4; p++) {
                    mma16(acc[0][2*p],   af[0][0], af[0][1], af[0][2], af[0][3],
                          f[p][0].x, f[p][0].y);
                    mma16(acc[1][2*p],   af[1][0], af[1][1], af[1][2], af[1][3],
                          f[p][0].x, f[p][0].y);
                    mma16(acc[0][2*p+1], af[0][0], af[0][1], af[0][2], af[0][3],
                          f[p][1].x, f[p][1].y);
                    mma16(acc[1][2*p+1], af[1][0], af[1][1], af[1][2], af[1][3],
                          f[p][1].x, f[p][1].y);
                }
            }
        }
        __syncthreads();    // all warps done reading actu

#pragma unroll
        for (int mt = 0; mt < 2; mt++) {
            const int r0 = m0 + mt*16 + g;
#pragma unroll
            for (int nt = 0; nt < 8; nt++) {
                const int col = n0b + nt*8 + 2*t;
                float v0 = fmaxf(acc[mt][nt][0] + bias_s[col],     0.f);
                float v1 = fmaxf(acc[mt][nt][1] + bias_s[col + 1], 0.f);
                float v2 = fmaxf(acc[mt][nt][2] + bias_s[col],     0.f);
                float v3 = fmaxf(acc[mt][nt][3] + bias_s[col + 1], 0.f);
                __half2 h01 = __floats2half2_rn(v0, v1);
                __half2 h23 = __floats2half2_rn(v2, v3);
                const int cw = (n0b >> 1) + nt*4 + t;
                actu[r0*(ASH/2) + cw]     = *(const uint32_t*)&h01;
                actu[(r0+8)*(ASH/2) + cw] = *(const uint32_t*)&h23;
            }
        }
        __syncthreads();    // acts ready for next layer / stage 3
    }

    // ---- stage 3: output layer 256->3 (fp32 accumulate over fp16 acts)
    {
        float* wsm = bias3;                 // reuse bias region (768 floats)
        for (int i = tid; i < 768; i += QTHREADS) wsm[i] = w4[i];
        __syncthreads();
        if (tid < SB) {
            const __half* ap = acth + tid*ASH;
            float s0 = b4[0], s1 = b4[1], s2 = b4[2];
#pragma unroll 4
            for (int k = 0; k < 256; k++) {
                float a = __half2float(ap[k]);
                s0 = fmaf(a, wsm[k*3 + 0], s0);
                s1 = fmaf(a, wsm[k*3 + 1], s1);
                s2 = fmaf(a, wsm[k*3 + 2], s2);
            }
            pred_s[tid][0] = s0; pred_s[tid][1] = s1; pred_s[tid][2] = s2;
        }
    }
    __syncthreads();

    if (tid < QB) {
        int bb = tid*4;
        float a0 = area_s[bb+0], a1 = area_s[bb+1];
        float a2 = area_s[bb+2], a3 = area_s[bb+3];
        float tot = a0 + a1 + a2 + a3 + 1e-9f;
        int q = blockIdx.x*QB + tid;
#pragma unroll
        for (int j = 0; j < 3; j++) {
            float num = pred_s[bb+0][j]*a3 + pred_s[bb+1][j]*a2
                      + pred_s[bb+2][j]*a1 + pred_s[bb+3][j]*a0;
            float yv = num / tot;
            yv = fminf(fmaxf(yv, 0.f), 1.f);
            out[(size_t)j*NQ + q] = yv;
        }
    }
}

// ------------------------------ launch --------------------------------------
extern "C" void kernel_launch(void* const* d_in, const int* in_sizes, int n_in,
                              void* d_out, int out_size)
{
    const float* x      = (const float*)d_in[0];
    const float* head_w = (const float*)d_in[2];
    const float* head_b = (const float*)d_in[3];
    const float* rb_w   = (const float*)d_in[4];
    const float* rb_b   = (const float*)d_in[5];
    const float* tail_w = (const float*)d_in[6];
    const float* tail_b = (const float*)d_in[7];
    const float* mw0 = (const float*)d_in[8];
    const float* mb0 = (const float*)d_in[9];
    const float* mw1 = (const float*)d_in[10];
    const float* mb1 = (const float*)d_in[11];
    const float* mw2 = (const float*)d_in[12];
    const float* mb2 = (const float*)d_in[13];
    const float* mw3 = (const float*)d_in[14];
    const float* mb3 = (const float*)d_in[15];
    const float* mw4 = (const float*)d_in[16];
    const float* mb4 = (const float*)d_in[17];
    float* out = (float*)d_out;

    float *h0, *b0eff;
    __half *h0h, *Ah, *Bh, *G, *w1h, *w2h, *w3h, *wch, *wl0;
    cudaGetSymbolAddress((void**)&h0, g_h0);
    cudaGetSymbolAddress((void**)&h0h, g_h0h);
    cudaGetSymbolAddress((void**)&Ah,  g_Ah);
    cudaGetSymbolAddress((void**)&Bh,  g_Bh);
    cudaGetSymbolAddress((void**)&G,  g_G);
    cudaGetSymbolAddress((void**)&b0eff, g_b0eff);
    cudaGetSymbolAddress((void**)&w1h, g_w1h);
    cudaGetSymbolAddress((void**)&w2h, g_w2h);
    cudaGetSymbolAddress((void**)&w3h, g_w3h);
    cudaGetSymbolAddress((void**)&wch, g_wch);
    cudaGetSymbolAddress((void**)&wl0, g_wl0);

    prep_all<<<(PREP_TOTAL + 255)/256, 256>>>(rb_w, tail_w, mw0, mb0,
                                              mw1, mw2, mw3,
                                              wch, wl0, w1h, w2h, w3h, b0eff);

    conv_head<<<dim3(W/CTX, H/CTY, 4), dim3(CTX, CTY)>>>(x, head_w, head_b,
                                                         h0, h0h);

    cudaFuncSetAttribute(fused_conv,
                         cudaFuncAttributeMaxDynamicSharedMemorySize, FSMEM);
    fused_conv<<<128, 256, FSMEM>>>(h0h, h0, wch, rb_b, tail_b, wl0,
                                    Ah, Bh, G);

    cudaFuncSetAttribute(query_kernel,
                         cudaFuncAttributeMaxDynamicSharedMemorySize,
                         DYN_BYTES);
    query_kernel<<<NQ/QB, QTHREADS, DYN_BYTES>>>(
        G, mw0, b0eff, w1h, mb1, w2h, mb2, w3h, mb3, mw4, mb4, out);
}

// round 16
// speedup vs baseline: 1.4288x; 1.0686x over previous
#include <cuda_runtime.h>
#include <cuda_fp16.h>
#include <cstdint>

#define H 128
#define W 128
#define HW 16384
#define OH 512
#define OWID 512
#define NQ (OH*OWID)

// ------------------------------ scratch (device globals, no allocation) ----
__device__ __align__(16) float g_h0[64*HW];      // fp32 NHWC (head conv out)
__device__ __align__(16) __half g_h0h[64*HW];    // fp16 NHWC
__device__ __align__(16) __half g_Ah [64*HW];    // ping-pong fp16 buffers
__device__ __align__(16) __half g_Bh [64*HW];
__device__ __align__(16) __half g_G [(size_t)HW*256];
__device__ float g_b0eff[256];
__device__ __align__(16) __half g_w1h[65536];    // fragment-packed MLP weights
__device__ __align__(16) __half g_w2h[65536];
__device__ __align__(16) __half g_w3h[65536];
__device__ __align__(16) __half g_wch[33*36864]; // fp16 conv weights [cv][tap][n][ic]
__device__ __align__(16) __half g_wl0[4*36864];  // fp16 layer-0 conv weights
__device__ unsigned g_bar_cnt;
__device__ volatile unsigned g_bar_gen;
__device__ int g_row_flag[128];

// ------------------------------ PTX helpers --------------------------------
__device__ __forceinline__ uint32_t smem_u32(const void* p) {
    uint32_t a;
    asm("{ .reg .u64 t; cvta.to.shared.u64 t, %1; cvt.u32.u64 %0, t; }"
        : "=r"(a) : "l"(p));
    return a;
}
__device__ __forceinline__ void cp_async16(uint32_t dst, const void* src) {
    asm volatile("cp.async.ca.shared.global [%0], [%1], 16;"
                 :: "r"(dst), "l"(src) : "memory");
}
__device__ __forceinline__ void cp_async16_cg(uint32_t dst, const void* src) {
    asm volatile("cp.async.cg.shared.global [%0], [%1], 16;"
                 :: "r"(dst), "l"(src) : "memory");
}
__device__ __forceinline__ void cp_commit() {
    asm volatile("cp.async.commit_group;" ::: "memory");
}
template<int N> __device__ __forceinline__ void cp_wait() {
    asm volatile("cp.async.wait_group %0;" :: "n"(N) : "memory");
}
// m16n8k16 f16 MMA, A row-major, B col-major, f32 accumulate (in-place)
__device__ __forceinline__ void mma16(float* d,
                                      uint32_t a0, uint32_t a1, uint32_t a2, uint32_t a3,
                                      uint32_t b0, uint32_t b1) {
    asm volatile(
        "mma.sync.aligned.m16n8k16.row.col.f32.f16.f16.f32 "
        "{%0,%1,%2,%3},{%4,%5,%6,%7},{%8,%9},{%0,%1,%2,%3};"
        : "+f"(d[0]), "+f"(d[1]), "+f"(d[2]), "+f"(d[3])
        : "r"(a0), "r"(a1), "r"(a2), "r"(a3), "r"(b0), "r"(b1));
}
// ldmatrix x4 (b16, non-transposed)
__device__ __forceinline__ void ldsm4(uint32_t& r0, uint32_t& r1,
                                      uint32_t& r2, uint32_t& r3, uint32_t addr) {
    asm volatile("ldmatrix.sync.aligned.m8n8.x4.shared.b16 {%0,%1,%2,%3}, [%4];"
                 : "=r"(r0), "=r"(r1), "=r"(r2), "=r"(r3) : "r"(addr));
}

// software grid barrier (all 128 CTAs resident; generation-based = replay-safe)
__device__ __forceinline__ void grid_barrier() {
    __syncthreads();
    if (threadIdx.x == 0) {
        __threadfence();
        unsigned gen = g_bar_gen;
        if (atomicAdd(&g_bar_cnt, 1u) == 127u) {
            atomicExch(&g_bar_cnt, 0u);
            __threadfence();
            g_bar_gen = gen + 1u;
        } else {
            while (g_bar_gen == gen) {}
        }
        __threadfence();
    }
    __syncthreads();
}

// ------------------------------ head conv (IC=3), NCHW in -> NHWC out -------
#define CTX 32
#define CTY 4
__global__ void conv_head(const float* __restrict__ x,
                          const float* __restrict__ w,
                          const float* __restrict__ bias,
                          float* __restrict__ out,
                          __half* __restrict__ outh)
{
    __shared__ float in_s[3][CTY+2][CTX+2];
    __shared__ float w_s[3*9*16];
    const int tx = threadIdx.x, ty = threadIdx.y;
    const int tid = ty*CTX + tx;
    const int x0 = blockIdx.x*CTX, y0 = blockIdx.y*CTY;
    const int ocg0 = blockIdx.z*16;

    float acc[16];
#pragma unroll
    for (int i = 0; i < 16; i++) acc[i] = 0.f;

    const int tot = 3*(CTY+2)*(CTX+2);
    for (int i = tid; i < tot; i += CTX*CTY) {
        int ic  = i / ((CTY+2)*(CTX+2));
        int rem = i % ((CTY+2)*(CTX+2));
        int ly = rem / (CTX+2), lx = rem % (CTX+2);
        int gy = y0 - 1 + ly, gx = x0 - 1 + lx;
        float v = 0.f;
        if (gy >= 0 && gy < H && gx >= 0 && gx < W)
            v = x[(size_t)ic*HW + gy*W + gx];
        in_s[ic][ly][lx] = v;
    }
    for (int i = tid; i < 3*9*16; i += CTX*CTY) {
        int oc = i & 15;
        int t2 = i >> 4;
        int tap = t2 % 9, ic = t2 / 9;
        w_s[(ic*9+tap)*16 + oc] = w[(size_t)(ocg0+oc)*27 + ic*9 + tap];
    }
    __syncthreads();
    for (int ic = 0; ic < 3; ic++) {
#pragma unroll
        for (int tap = 0; tap < 9; tap++) {
            const int dy = tap/3, dx = tap%3;
            float a = in_s[ic][ty+dy][tx+dx];
            const float4* wp = (const float4*)&w_s[(ic*9+tap)*16];
            float wv[16];
            *(float4*)&wv[0]  = wp[0];
            *(float4*)&wv[4]  = wp[1];
            *(float4*)&wv[8]  = wp[2];
            *(float4*)&wv[12] = wp[3];
#pragma unroll
            for (int oc = 0; oc < 16; oc++)
                acc[oc] = fmaf(a, wv[oc], acc[oc]);
        }
    }
    const int pix = (y0+ty)*W + (x0+tx);
    float4* o4 = (float4*)(out + (size_t)pix*64 + ocg0);
    __half2* oh2 = (__half2*)(outh + (size_t)pix*64 + ocg0);
#pragma unroll
    for (int v = 0; v < 4; v++) {
        float4 r;
        r.x = acc[v*4+0] + bias[ocg0+v*4+0];
        r.y = acc[v*4+1] + bias[ocg0+v*4+1];
        r.z = acc[v*4+2] + bias[ocg0+v*4+2];
        r.w = acc[v*4+3] + bias[ocg0+v*4+3];
        o4[v] = r;
        oh2[v*2]   = __floats2half2_rn(r.x, r.y);
        oh2[v*2+1] = __floats2half2_rn(r.z, r.w);
    }
}

// ------------------------------ merged weight transforms --------------------
#define N_WCH (33*36864)
#define N_WL0 (4*36864)
#define N_W123 (3*65536)
#define PREP_TOTAL (N_WCH + N_WL0 + N_W123 + 256)

__global__ void prep_all(const float* __restrict__ rb_w,
                         const float* __restrict__ tail_w,
                         const float* __restrict__ mw0,
                         const float* __restrict__ mb0,
                         const float* __restrict__ mw1,
                         const float* __restrict__ mw2,
                         const float* __restrict__ mw3,
                         __half* __restrict__ wch,
                         __half* __restrict__ wl0,
                         __half* __restrict__ wh1,
                         __half* __restrict__ wh2,
                         __half* __restrict__ wh3,
                         float* __restrict__ b0eff)
{
    int i = blockIdx.x*256 + threadIdx.x;
    if (i < N_WCH) {
        int cv = i / 36864;
        int r  = i % 36864;
        int tap = r >> 12;
        int r2  = r & 4095;
        int n   = r2 >> 6;
        int ic  = r2 & 63;
        const float* src = (cv < 32) ? (rb_w + (size_t)cv*36864) : tail_w;
        wch[i] = __float2half(src[(size_t)n*576 + ic*9 + tap]);
        return;
    }
    i -= N_WCH;
    if (i < N_WL0) {
        int grp = i / 36864;
        int r  = i % 36864;
        int tap = r >> 12;
        int r2  = r & 4095;
        int n   = r2 >> 6;
        int ic  = r2 & 63;
        int ng = grp*64 + n;
        wl0[i] = __float2half(mw0[(size_t)(ic*9 + tap)*256 + ng]);
        return;
    }
    i -= N_WL0;
    if (i < N_W123) {
        // uint4 fragment-packed B: entry = ((c*16 + jp)*4 + ks)*32 + lane,
        // 8 halfs/entry: j=2jp+(hh>>2), row=j*8+(lane>>2),
        // k = c*64 + ks*16 + 2*(lane&3) + (hh&1) + ((hh>>1)&1)*8
        int which = i >> 16;
        int idx = i & 65535;
        int hh    = idx & 7;
        int entry = idx >> 3;
        int lane = entry & 31;
        int ks   = (entry >> 5) & 3;
        int jp   = (entry >> 7) & 15;
        int c    = entry >> 11;
        int gg = lane >> 2, tt = lane & 3;
        int row = (jp*2 + (hh >> 2))*8 + gg;
        int k = c*64 + ks*16 + 2*tt + (hh & 1) + ((hh >> 1) & 1)*8;
        const float* w = (which == 0) ? mw1 : (which == 1) ? mw2 : mw3;
        __half* wh = (which == 0) ? wh1 : (which == 1) ? wh2 : wh3;
        wh[idx] = __float2half(w[k*256 + row]);
        return;
    }
    i -= N_W123;
    if (i < 256)
        b0eff[i] = mb0[i] + 0.5f*mw0[578*256 + i] + 0.5f*mw0[579*256 + i];
}

// ------------------------------ fused persistent conv chain -----------------
// 128 CTAs, one per image row, neighbor-flag synchronized.
#define PXW 36
#define STRIPW2 (3*130*PXW)              // 14040 words
#define WTW (9*64*PXW)                   // 20736 words
#define RSW 68
#define OFF_RES (STRIPW2 + WTW)
#define OFF_H0  (OFF_RES + 128*RSW)
#define FSM_WORDS (OFF_H0 + 128*RSW)
#define FSMEM (FSM_WORDS*4)              // 208736 bytes

__global__ void __launch_bounds__(256) fused_conv(
    const __half* __restrict__ h0h, const float* __restrict__ h0f,
    const __half* __restrict__ wch, const float* __restrict__ rb_b,
    const float* __restrict__ tail_b, const __half* __restrict__ wl0,
    __half* __restrict__ bufA, __half* __restrict__ bufB,
    __half* __restrict__ G)
{
    extern __shared__ uint32_t sm[];
    uint32_t* strip = sm;
    uint32_t* wsm   = sm + STRIPW2;
    float* res_s = (float*)(sm + OFF_RES);
    float* h0_s  = (float*)(sm + OFF_H0);
    __shared__ float bias_s[64];

    const int tid = threadIdx.x, wid = tid >> 5, lane = tid & 31;
    const int g = lane >> 2, t = lane & 3;
    const int y = blockIdx.x;
    const uint32_t smaddr  = smem_u32(sm);
    const uint32_t wbase   = smaddr + STRIPW2*4;
    const uint32_t resaddr = smaddr + OFF_RES*4;
    const uint32_t h0addr  = smaddr + OFF_H0*4;

    {
        uint4 z = {0, 0, 0, 0};
        uint4* s4 = (uint4*)sm;
        for (int i = tid; i < STRIPW2/4; i += 256) s4[i] = z;
    }
    __syncthreads();

    for (int i = tid; i < 3120; i += 256) {
        int r = i / 1040, rem = i - r*1040;
        int j = rem >> 3, c = rem & 7;
        int gy = y - 1 + r, gx = j - 1;
        if (gy >= 0 && gy < H && gx >= 0 && gx < W)
            cp_async16(smaddr + (uint32_t)((r*130 + j)*PXW + c*4)*4,
                       h0h + ((size_t)(gy*W + gx))*64 + c*8);
    }
    for (int i = tid; i < 2048; i += 256) {
        int px = i >> 4, c = i & 15;
        const float* src = h0f + ((size_t)(y*W + px))*64 + c*4;
        cp_async16(resaddr + (uint32_t)(px*RSW + c*4)*4, src);
        cp_async16(h0addr  + (uint32_t)(px*RSW + c*4)*4, src);
    }
    for (int i = tid; i < 4608; i += 256) {
        int n2 = i >> 3, j = i & 7;
        cp_async16(wbase + (uint32_t)(n2*PXW + j*4)*4, wch + n2*64 + j*8);
    }
    cp_commit();

    if (tid == 0) g_row_flag[y] = 0;
    grid_barrier();

    cp_wait<0>();
    __syncthreads();

    const int m0 = (wid & 3)*32, n0 = (wid >> 2)*32;
    __half* bufs[2] = {bufA, bufB};

    for (int l = 0; l < 33; l++) {
        if (tid < 64) bias_s[tid] = (l < 32) ? rb_b[l*64 + tid] : tail_b[tid];

        float acc[2][4][4];
#pragma unroll
        for (int a = 0; a < 2; a++)
#pragma unroll
            for (int b = 0; b < 4; b++)
#pragma unroll
                for (int c = 0; c < 4; c++) acc[a][b][c] = 0.f;

        for (int tap = 0; tap < 9; tap++) {
            const int dy = tap/3, dx = tap%3;
            const uint32_t* wb = wsm + tap*(64*PXW);
            const uint32_t* arow0 = strip + (uint32_t)(dy*130 + dx)*PXW;
#pragma unroll
            for (int ks = 0; ks < 4; ks++) {
                const int kw = ks*8 + t;
                uint32_t af[2][4];
#pragma unroll
                for (int mt = 0; mt < 2; mt++) {
                    const uint32_t* ar = arow0 + (uint32_t)(m0 + mt*16 + g)*PXW + kw;
                    af[mt][0] = ar[0];
                    af[mt][1] = ar[8*PXW];
                    af[mt][2] = ar[4];
                    af[mt][3] = ar[8*PXW + 4];
                }
#pragma unroll
                for (int nt = 0; nt < 4; nt++) {
                    const uint32_t* bw = wb + (uint32_t)(n0 + nt*8 + g)*PXW + kw;
                    uint32_t b0 = bw[0], b1 = bw[4];
                    mma16(acc[0][nt], af[0][0], af[0][1], af[0][2], af[0][3], b0, b1);
                    mma16(acc[1][nt], af[1][0], af[1][1], af[1][2], af[1][3], b0, b1);
                }
            }
        }
        __syncthreads();

        const __half* wnext = (l < 32) ? (wch + (size_t)(l + 1)*36864) : wl0;
        for (int i = tid; i < 4608; i += 256) {
            int n2 = i >> 3, j = i & 7;
            cp_async16(wbase + (uint32_t)(n2*PXW + j*4)*4, wnext + n2*64 + j*8);
        }
        cp_commit();

        __half* outb = bufs[l & 1];
        const int mode = (l == 32) ? 2 : (l & 1);
#pragma unroll
        for (int mt = 0; mt < 2; mt++) {
            const int p1 = m0 + mt*16 + g;
            const int p2 = p1 + 8;
#pragma unroll
            for (int nt = 0; nt < 4; nt++) {
                const int c0 = n0 + nt*8 + 2*t;
                float v0 = acc[mt][nt][0], v1 = acc[mt][nt][1];
                float v2 = acc[mt][nt][2], v3 = acc[mt][nt][3];
                float b0 = bias_s[c0], b1 = bias_s[c0 + 1];
                if (mode == 0) {
                    v0 = fmaxf(v0 + b0, 0.f); v1 = fmaxf(v1 + b1, 0.f);
                    v2 = fmaxf(v2 + b0, 0.f); v3 = fmaxf(v3 + b1, 0.f);
                } else if (mode == 1) {
                    float2 r0 = *(const float2*)(res_s + p1*RSW + c0);
                    float2 r1 = *(const float2*)(res_s + p2*RSW + c0);
                    v0 += b0 + r0.x; v1 += b1 + r0.y;
                    v2 += b0 + r1.x; v3 += b1 + r1.y;
                    float2 s0 = {v0, v1}, s1 = {v2, v3};
                    *(float2*)(res_s + p1*RSW + c0) = s0;
                    *(float2*)(res_s + p2*RSW + c0) = s1;
                } else {
                    float2 r0 = *(const float2*)(h0_s + p1*RSW + c0);
                    float2 r1 = *(const float2*)(h0_s + p2*RSW + c0);
                    v0 += b0 + r0.x; v1 += b1 + r0.y;
                    v2 += b0 + r1.x; v3 += b1 + r1.y;
                }
                __half2 h0v = __floats2half2_rn(v0, v1);
                __half2 h1v = __floats2half2_rn(v2, v3);
                *(__half2*)(outb + ((size_t)(y*W + p1))*64 + c0) = h0v;
                *(__half2*)(outb + ((size_t)(y*W + p2))*64 + c0) = h1v;
                const int cw = (c0 >> 1);
                strip[(uint32_t)(130 + 1 + p1)*PXW + cw] = *(const uint32_t*)&h0v;
                strip[(uint32_t)(130 + 1 + p2)*PXW + cw] = *(const uint32_t*)&h1v;
            }
        }
        __threadfence();
        __syncthreads();
        if (tid == 0) {
            atomicExch(&g_row_flag[y], l + 1);
            if (y > 0)
                while (*(volatile int*)&g_row_flag[y - 1] < l + 1) {}
            __threadfence();
        }
        if (tid == 32 && y < 127) {
            while (*(volatile int*)&g_row_flag[y + 1] < l + 1) {}
            __threadfence();
        }
        __syncthreads();

        for (int i = tid; i < 2080; i += 256) {
            int rr = i / 1040, rem = i - rr*1040;
            int j = rem >> 3, c = rem & 7;
            int r = rr*2;
            int gy = y - 1 + r, gx = j - 1;
            if (gy >= 0 && gy < H && gx >= 0 && gx < W)
                cp_async16_cg(smaddr + (uint32_t)((r*130 + j)*PXW + c*4)*4,
                              outb + ((size_t)(gy*W + gx))*64 + c*8);
        }
        cp_commit();
        cp_wait<0>();
        __syncthreads();
    }

    for (int grp = 0; grp < 4; grp++) {
        float acc[2][4][4];
#pragma unroll
        for (int a = 0; a < 2; a++)
#pragma unroll
            for (int b = 0; b < 4; b++)
#pragma unroll
                for (int c = 0; c < 4; c++) acc[a][b][c] = 0.f;

        for (int tap = 0; tap < 9; tap++) {
            const int dy = tap/3, dx = tap%3;
            const uint32_t* wb = wsm + tap*(64*PXW);
            const uint32_t* arow0 = strip + (uint32_t)(dy*130 + dx)*PXW;
#pragma unroll
            for (int ks = 0; ks < 4; ks++) {
                const int kw = ks*8 + t;
                uint32_t af[2][4];
#pragma unroll
                for (int mt = 0; mt < 2; mt++) {
                    const uint32_t* ar = arow0 + (uint32_t)(m0 + mt*16 + g)*PXW + kw;
                    af[mt][0] = ar[0];
                    af[mt][1] = ar[8*PXW];
                    af[mt][2] = ar[4];
                    af[mt][3] = ar[8*PXW + 4];
                }
#pragma unroll
                for (int nt = 0; nt < 4; nt++) {
                    const uint32_t* bw = wb + (uint32_t)(n0 + nt*8 + g)*PXW + kw;
                    uint32_t b0 = bw[0], b1 = bw[4];
                    mma16(acc[0][nt], af[0][0], af[0][1], af[0][2], af[0][3], b0, b1);
                    mma16(acc[1][nt], af[1][0], af[1][1], af[1][2], af[1][3], b0, b1);
                }
            }
        }
        __syncthreads();

        if (grp < 3) {
            const __half* wnext = wl0 + (size_t)(grp + 1)*36864;
            for (int i = tid; i < 4608; i += 256) {
                int n2 = i >> 3, j = i & 7;
                cp_async16(wbase + (uint32_t)(n2*PXW + j*4)*4, wnext + n2*64 + j*8);
            }
            cp_commit();
        }

#pragma unroll
        for (int mt = 0; mt < 2; mt++) {
            const int p1 = m0 + mt*16 + g;
            const int p2 = p1 + 8;
#pragma unroll
            for (int nt = 0; nt < 4; nt++) {
                const int c0 = n0 + nt*8 + 2*t;
                const int cc = grp*64 + c0;
                __half2 h0v = __floats2half2_rn(acc[mt][nt][0], acc[mt][nt][1]);
                __half2 h1v = __floats2half2_rn(acc[mt][nt][2], acc[mt][nt][3]);
                *(__half2*)(G + ((size_t)(y*W + p1))*256 + cc) = h0v;
                *(__half2*)(G + ((size_t)(y*W + p2))*256 + cc) = h1v;
            }
        }
        if (grp < 3) {
            cp_wait<0>();
            __syncthreads();
        }
    }
}

// ------------------------------ LIIF query + mma.sync fp16 MLP --------------
// 256 threads / 8 warps, SB=64: 2 M-groups x 4 N-groups. B via uint4 LDG from
// fragment-packed global layout; stage 3 computed from L3 accumulators.
#define QB 16
#define SB 64
#define QTHREADS 256
#define ASH 264
#define OFF_ACT 0
#define OFF_BIAS 33792                    // bias3 [3][256] floats
#define OFF_W4   36864                    // w4 staged [768] floats
#define OFF_PART 39936                    // part [64][3] floats (atomic)
#define DYN_BYTES 40704

__global__ __launch_bounds__(QTHREADS, 2)
void query_kernel(const __half* __restrict__ G,
                  const float* __restrict__ mw0,
                  const float* __restrict__ b0eff,
                  const __half* __restrict__ w1h, const float* __restrict__ b1,
                  const __half* __restrict__ w2h, const float* __restrict__ b2,
                  const __half* __restrict__ w3h, const float* __restrict__ b3,
                  const float* __restrict__ w4, const float* __restrict__ b4,
                  float* __restrict__ out)
{
    extern __shared__ char dyn[];
    uint32_t* actu = (uint32_t*)(dyn + OFF_ACT);
    float*    bias3 = (float*)(dyn + OFF_BIAS);   // [3][256]
    float*    w4_s  = (float*)(dyn + OFF_W4);     // [768]
    float*    part  = (float*)(dyn + OFF_PART);   // [64][3]
    __shared__ int   p_s[SB];
    __shared__ float relh_s[SB], relw_s[SB], area_s[SB];
    __shared__ float pred_s[SB][4];

    const int tid  = threadIdx.x;
    const int wid  = tid >> 5;
    const int lane = tid & 31;
    const int g    = lane >> 2;
    const int t    = lane & 3;
    const int mi   = lane >> 3;      // ldmatrix matrix index
    const int rr   = lane & 7;       // ldmatrix row within matrix

    const uint32_t dynaddr = smem_u32(dyn);

    if (tid < SB) {
        int m  = tid;
        int q  = blockIdx.x*QB + (m >> 2);
        int oh = q >> 9, ow = q & 511;
        int r  = (m >> 1) & 1, c = m & 1;
        float sh = (oh + 0.5f)*(2.0f/512.0f) - 1.0f;
        float sw = (ow + 0.5f)*(2.0f/512.0f) - 1.0f;
        const float d = 1.0f/128.0f, EPS = 1e-6f;
        float gh = fminf(fmaxf(sh + (2.f*r - 1.f)*d, -1.f + EPS), 1.f - EPS);
        float gw = fminf(fmaxf(sw + (2.f*c - 1.f)*d, -1.f + EPS), 1.f - EPS);
        float fy = ((gh + 1.0f)*128.0f - 1.0f)*0.5f;
        float fx = ((gw + 1.0f)*128.0f - 1.0f)*0.5f;
        int iy = min(max((int)rintf(fy), 0), 127);
        int ix = min(max((int)rintf(fx), 0), 127);
        float qgh = (iy + 0.5f)*(2.0f/128.0f) - 1.0f;
        float qgw = (ix + 0.5f)*(2.0f/128.0f) - 1.0f;
        float rh = (sh - qgh)*128.0f;
        float rw = (sw - qgw)*128.0f;
        p_s[m] = iy*128 + ix;
        relh_s[m] = rh; relw_s[m] = rw;
        area_s[m] = fabsf(rh*rw);
    }
    // preload all 3 layer biases, w4, zero partials
    bias3[tid]       = b1[tid];
    bias3[256 + tid] = b2[tid];
    bias3[512 + tid] = b3[tid];
    for (int i = tid; i < 768; i += QTHREADS) w4_s[i] = w4[i];
    if (tid < 192) part[tid] = 0.f;
    __syncthreads();

    // ---- stage 1: A0 = relu(G[p] + rel_h*U + rel_w*V + b0eff) -> fp16
    {
        const int ocw = tid & 127;
        const int oc0 = ocw*2;
        float u0 = mw0[576*256 + oc0],     u1 = mw0[576*256 + oc0 + 1];
        float v0 = mw0[577*256 + oc0],     v1 = mw0[577*256 + oc0 + 1];
        float b0v = b0eff[oc0],            b1v = b0eff[oc0 + 1];
        const __half2* G2 = (const __half2*)G;
        for (int m = (tid >> 7); m < SB; m += 2) {
            __half2 gg = G2[(size_t)p_s[m]*128 + ocw];
            float rh = relh_s[m], rw = relw_s[m];
            float x0v = fmaf(rh, u0, fmaf(rw, v0, __low2float(gg)  + b0v));
            float x1v = fmaf(rh, u1, fmaf(rw, v1, __high2float(gg) + b1v));
            __half2 hv = __floats2half2_rn(fmaxf(x0v, 0.f), fmaxf(x1v, 0.f));
            actu[m*(ASH/2) + ocw] = *(const uint32_t*)&hv;
        }
    }
    __syncthreads();

    const int m0  = (wid & 1)*32;     // 2 M-groups over 64 samples
    const int n0b = (wid >> 1)*64;    // 4 N-groups over 256 neurons
    const int jpb = (wid >> 1)*4;     // uint4 fragment-packed jp base

    // ---- ldmatrix lane addresses for A (bytes)
    uint32_t aAddr[2];
#pragma unroll
    for (int mt = 0; mt < 2; mt++) {
        int row = m0 + mt*16 + (mi & 1)*8 + rr;
        aAddr[mt] = dynaddr + OFF_ACT
                  + (uint32_t)(row*(ASH/2) + (mi >> 1)*4)*4u;
    }

    const __half* Ws[3] = {w1h, w2h, w3h};

    for (int L = 0; L < 3; L++) {
        const uint4* Wq = (const uint4*)Ws[L];
        const float* bias_s = bias3 + L*256;

        float acc[2][8][4];
#pragma unroll
        for (int mt = 0; mt < 2; mt++)
#pragma unroll
            for (int nt = 0; nt < 8; nt++)
#pragma unroll
                for (int i = 0; i < 4; i++) acc[mt][nt][i] = 0.f;

#pragma unroll
        for (int c = 0; c < 4; c++) {
#pragma unroll
            for (int ks = 0; ks < 4; ks++) {
                const uint32_t kbyte = (uint32_t)(c*32 + ks*8)*4u;
                uint32_t af[2][4];
                ldsm4(af[0][0], af[0][1], af[0][2], af[0][3], aAddr[0] + kbyte);
                ldsm4(af[1][0], af[1][1], af[1][2], af[1][3], aAddr[1] + kbyte);
                uint4 f[4];
#pragma unroll
                for (int p = 0; p < 4; p++)
                    f[p] = __ldg(Wq + ((size_t)((c*16 + jpb + p)*4 + ks)*32 + lane));
#pragma unroll
                for (int p = 0; p < 4; p++) {
                    mma16(acc[0][2*p],   af[0][0], af[0][1], af[0][2], af[0][3],
                          f[p].x, f[p].y);
                    mma16(acc[1][2*p],   af[1][0], af[1][1], af[1][2], af[1][3],
                          f[p].x, f[p].y);
                    mma16(acc[0][2*p+1], af[0][0], af[0][1], af[0][2], af[0][3],
                          f[p].z, f[p].w);
                    mma16(acc[1][2*p+1], af[1][0], af[1][1], af[1][2], af[1][3],
                          f[p].z, f[p].w);
                }
            }
        }
        __syncthreads();    // all warps done reading actu

        if (L < 2) {
#pragma unroll
            for (int mt = 0; mt < 2; mt++) {
                const int r0 = m0 + mt*16 + g;
#pragma unroll
                for (int nt = 0; nt < 8; nt++) {
                    const int col = n0b + nt*8 + 2*t;
                    float v0 = fmaxf(acc[mt][nt][0] + bias_s[col],     0.f);
                    float v1 = fmaxf(acc[mt][nt][1] + bias_s[col + 1], 0.f);
                    float v2 = fmaxf(acc[mt][nt][2] + bias_s[col],     0.f);
                    float v3 = fmaxf(acc[mt][nt][3] + bias_s[col + 1], 0.f);
                    __half2 h01 = __floats2half2_rn(v0, v1);
                    __half2 h23 = __floats2half2_rn(v2, v3);
                    const int cw = (n0b >> 1) + nt*4 + t;
                    actu[r0*(ASH/2) + cw]     = *(const uint32_t*)&h01;
                    actu[(r0+8)*(ASH/2) + cw] = *(const uint32_t*)&h23;
                }
            }
            __syncthreads();
        } else {
            // ---- stage 3 fused: relu(acc+bias) folded into w4 partials
            float s[2][3];
#pragma unroll
            for (int q2 = 0; q2 < 2; q2++)
#pragma unroll
                for (int j = 0; j < 3; j++) s[q2][j] = 0.f;
#pragma unroll
            for (int mt = 0; mt < 2; mt++) {
                // rows: ra = m0+mt*16+g (acc i=0,1), rb = ra+8 (i=2,3)
#pragma unroll
                for (int nt = 0; nt < 8; nt++) {
                    const int col = n0b + nt*8 + 2*t;
                    float v0 = fmaxf(acc[mt][nt][0] + bias_s[col],     0.f);
                    float v1 = fmaxf(acc[mt][nt][1] + bias_s[col + 1], 0.f);
                    float v2 = fmaxf(acc[mt][nt][2] + bias_s[col],     0.f);
                    float v3 = fmaxf(acc[mt][nt][3] + bias_s[col + 1], 0.f);
#pragma unroll
                    for (int j = 0; j < 3; j++) {
                        float wj0 = w4_s[col*3 + j];
                        float wj1 = w4_s[(col+1)*3 + j];
                        // fold mt via separate accumulators per (mt, half)
                        // s index: q2 = 2*mt + (0 for ra, 1 for rb) -> need 4;
                        // reuse: accumulate into s with mt folded sequentially.
                        if (mt == 0) {
                            s[0][j] = fmaf(v0, wj0, fmaf(v1, wj1, s[0][j]));
                            s[1][j] = fmaf(v2, wj0, fmaf(v3, wj1, s[1][j]));
                        } else {
                            // handled below via second pass arrays
                            s[0][j] = s[0][j];  // placeholder (restructured)
                        }
                    }
                }
                if (mt == 0) {
                    // quad-reduce over t lanes and commit rows ra, rb
                    const int ra = m0 + g;
#pragma unroll
                    for (int q2 = 0; q2 < 2; q2++) {
#pragma unroll
                        for (int j = 0; j < 3; j++) {
                            float v = s[q2][j];
                            v += __shfl_xor_sync(0xFFFFFFFF, v, 1);
                            v += __shfl_xor_sync(0xFFFFFFFF, v, 2);
                            if (t == 0)
                                atomicAdd(&part[(ra + q2*8)*3 + j], v);
                            s[q2][j] = 0.f;
                        }
                    }
                } else {
                    // recompute mt=1 contributions (loop above skipped them)
#pragma unroll
                    for (int nt = 0; nt < 8; nt++) {
                        const int col = n0b + nt*8 + 2*t;
                        float v0 = fmaxf(acc[1][nt][0] + bias_s[col],     0.f);
                        float v1 = fmaxf(acc[1][nt][1] + bias_s[col + 1], 0.f);
                        float v2 = fmaxf(acc[1][nt][2] + bias_s[col],     0.f);
                        float v3 = fmaxf(acc[1][nt][3] + bias_s[col + 1], 0.f);
#pragma unroll
                        for (int j = 0; j < 3; j++) {
                            float wj0 = w4_s[col*3 + j];
                            float wj1 = w4_s[(col+1)*3 + j];
                            s[0][j] = fmaf(v0, wj0, fmaf(v1, wj1, s[0][j]));
                            s[1][j] = fmaf(v2, wj0, fmaf(v3, wj1, s[1][j]));
                        }
                    }
                    const int ra = m0 + 16 + g;
#pragma unroll
                    for (int q2 = 0; q2 < 2; q2++) {
#pragma unroll
                        for (int j = 0; j < 3; j++) {
                            float v = s[q2][j];
                            v += __shfl_xor_sync(0xFFFFFFFF, v, 1);
                            v += __shfl_xor_sync(0xFFFFFFFF, v, 2);
                            if (t == 0)
                                atomicAdd(&part[(ra + q2*8)*3 + j], v);
                        }
                    }
                }
            }
            __syncthreads();
        }
    }

    // ---- finalize preds
    if (tid < SB) {
#pragma unroll
        for (int j = 0; j < 3; j++)
            pred_s[tid][j] = b4[j] + part[tid*3 + j];
    }
    __syncthreads();

    if (tid < QB) {
        int bb = tid*4;
        float a0 = area_s[bb+0], a1 = area_s[bb+1];
        float a2 = area_s[bb+2], a3 = area_s[bb+3];
        float tot = a0 + a1 + a2 + a3 + 1e-9f;
        int q = blockIdx.x*QB + tid;
#pragma unroll
        for (int j = 0; j < 3; j++) {
            float num = pred_s[bb+0][j]*a3 + pred_s[bb+1][j]*a2
                      + pred_s[bb+2][j]*a1 + pred_s[bb+3][j]*a0;
            float yv = num / tot;
            yv = fminf(fmaxf(yv, 0.f), 1.f);
            out[(size_t)j*NQ + q] = yv;
        }
    }
}

// ------------------------------ launch --------------------------------------
extern "C" void kernel_launch(void* const* d_in, const int* in_sizes, int n_in,
                              void* d_out, int out_size)
{
    const float* x      = (const float*)d_in[0];
    const float* head_w = (const float*)d_in[2];
    const float* head_b = (const float*)d_in[3];
    const float* rb_w   = (const float*)d_in[4];
    const float* rb_b   = (const float*)d_in[5];
    const float* tail_w = (const float*)d_in[6];
    const float* tail_b = (const float*)d_in[7];
    const float* mw0 = (const float*)d_in[8];
    const float* mb0 = (const float*)d_in[9];
    const float* mw1 = (const float*)d_in[10];
    const float* mb1 = (const float*)d_in[11];
    const float* mw2 = (const float*)d_in[12];
    const float* mb2 = (const float*)d_in[13];
    const float* mw3 = (const float*)d_in[14];
    const float* mb3 = (const float*)d_in[15];
    const float* mw4 = (const float*)d_in[16];
    const float* mb4 = (const float*)d_in[17];
    float* out = (float*)d_out;

    float *h0, *b0eff;
    __half *h0h, *Ah, *Bh, *G, *w1h, *w2h, *w3h, *wch, *wl0;
    cudaGetSymbolAddress((void**)&h0, g_h0);
    cudaGetSymbolAddress((void**)&h0h, g_h0h);
    cudaGetSymbolAddress((void**)&Ah,  g_Ah);
    cudaGetSymbolAddress((void**)&Bh,  g_Bh);
    cudaGetSymbolAddress((void**)&G,  g_G);
    cudaGetSymbolAddress((void**)&b0eff, g_b0eff);
    cudaGetSymbolAddress((void**)&w1h, g_w1h);
    cudaGetSymbolAddress((void**)&w2h, g_w2h);
    cudaGetSymbolAddress((void**)&w3h, g_w3h);
    cudaGetSymbolAddress((void**)&wch, g_wch);
    cudaGetSymbolAddress((void**)&wl0, g_wl0);

    prep_all<<<(PREP_TOTAL + 255)/256, 256>>>(rb_w, tail_w, mw0, mb0,
                                              mw1, mw2, mw3,
                                              wch, wl0, w1h, w2h, w3h, b0eff);

    conv_head<<<dim3(W/CTX, H/CTY, 4), dim3(CTX, CTY)>>>(x, head_w, head_b,
                                                         h0, h0h);

    cudaFuncSetAttribute(fused_conv,
                         cudaFuncAttributeMaxDynamicSharedMemorySize, FSMEM);
    fused_conv<<<128, 256, FSMEM>>>(h0h, h0, wch, rb_b, tail_b, wl0,
                                    Ah, Bh, G);

    cudaFuncSetAttribute(query_kernel,
                         cudaFuncAttributeMaxDynamicSharedMemorySize,
                         DYN_BYTES);
    query_kernel<<<NQ/QB, QTHREADS, DYN_BYTES>>>(
        G, mw0, b0eff, w1h, mb1, w2h, mb2, w3h, mb3, mw4, mb4, out);
}